// round 1
// baseline (speedup 1.0000x reference)
#include <cuda_runtime.h>
#include <math.h>

#define N_NODES_MAX 100000
#define F_IN  512
#define F_HID 128
#define F_OUT 32

// Scratch (allocation-free rule: __device__ globals)
__device__ float g_support[(size_t)N_NODES_MAX * F_HID];  // x @ W1
__device__ float g_h[(size_t)N_NODES_MAX * F_HID];        // A @ support + b1 (pre-relu)
__device__ float g_t[(size_t)N_NODES_MAX * F_OUT];        // relu(h) @ W2
__device__ float g_logits[(size_t)N_NODES_MAX * F_OUT];   // A @ t + b2

// ---------------------------------------------------------------------------
// Fill dst[i] = bias[i % F]  (F power of two). Doubles as zero/bias init for
// the atomic scatter targets.
// ---------------------------------------------------------------------------
__global__ void init_bias_kernel(float* __restrict__ dst,
                                 const float* __restrict__ bias,
                                 int fmask, int total) {
    int i = blockIdx.x * blockDim.x + threadIdx.x;
    if (i < total) dst[i] = bias[i & fmask];
}

// ---------------------------------------------------------------------------
// GEMM1: C[M,128] = A[M,512] @ B[512,128], fp32.
// 128x128 block tile, BK=8, 256 threads, 8x8 register tile per thread.
// ---------------------------------------------------------------------------
__global__ __launch_bounds__(256) void gemm1_kernel(const float* __restrict__ A,
                                                    const float* __restrict__ B,
                                                    float* __restrict__ C,
                                                    int M) {
    __shared__ float As[8][128];
    __shared__ float Bs[8][128];
    const int tid  = threadIdx.x;
    const int row0 = blockIdx.x * 128;
    const int tr = (tid >> 4) << 3;   // 0..120
    const int tc = (tid & 15) << 3;   // 0..120

    float acc[8][8];
#pragma unroll
    for (int i = 0; i < 8; i++)
#pragma unroll
        for (int j = 0; j < 8; j++) acc[i][j] = 0.f;

    const int a_row = tid >> 1;           // 0..127
    const int a_col = (tid & 1) << 2;     // 0 or 4
    const int b_row = tid >> 5;           // 0..7
    const int b_col = (tid & 31) << 2;    // 0..124
    const int grow  = row0 + a_row;
    const bool aok  = (grow < M);
    const float* Ap = A + (size_t)grow * F_IN + a_col;

    for (int k0 = 0; k0 < F_IN; k0 += 8) {
        float4 av = make_float4(0.f, 0.f, 0.f, 0.f);
        if (aok) av = *(const float4*)(Ap + k0);
        float4 bv = *(const float4*)(B + (size_t)(k0 + b_row) * F_HID + b_col);

        __syncthreads();
        As[a_col + 0][a_row] = av.x;
        As[a_col + 1][a_row] = av.y;
        As[a_col + 2][a_row] = av.z;
        As[a_col + 3][a_row] = av.w;
        *(float4*)&Bs[b_row][b_col] = bv;
        __syncthreads();

#pragma unroll
        for (int k = 0; k < 8; k++) {
            float ar[8], br[8];
            *(float4*)&ar[0] = *(const float4*)&As[k][tr];
            *(float4*)&ar[4] = *(const float4*)&As[k][tr + 4];
            *(float4*)&br[0] = *(const float4*)&Bs[k][tc];
            *(float4*)&br[4] = *(const float4*)&Bs[k][tc + 4];
#pragma unroll
            for (int i = 0; i < 8; i++)
#pragma unroll
                for (int j = 0; j < 8; j++)
                    acc[i][j] = fmaf(ar[i], br[j], acc[i][j]);
        }
    }

#pragma unroll
    for (int i = 0; i < 8; i++) {
        int r = row0 + tr + i;
        if (r < M) {
            *(float4*)&C[(size_t)r * F_HID + tc] =
                make_float4(acc[i][0], acc[i][1], acc[i][2], acc[i][3]);
            *(float4*)&C[(size_t)r * F_HID + tc + 4] =
                make_float4(acc[i][4], acc[i][5], acc[i][6], acc[i][7]);
        }
    }
}

// ---------------------------------------------------------------------------
// SpMM F=128: one warp per edge. Each lane: float4 gather from src[col],
// scale by val, 4 scalar atomicAdds into dst[row].
// ---------------------------------------------------------------------------
__global__ void spmm_f128_kernel(const int* __restrict__ erow,
                                 const int* __restrict__ ecol,
                                 const float* __restrict__ eval,
                                 const float* __restrict__ src,
                                 float* __restrict__ dst, int E) {
    long long gid = (long long)blockIdx.x * blockDim.x + threadIdx.x;
    int e    = (int)(gid >> 5);
    int lane = (int)(gid & 31);
    if (e >= E) return;
    int r   = erow[e];
    int c   = ecol[e];
    float v = eval[e];
    float4 s = *(const float4*)(src + (size_t)c * F_HID + lane * 4);
    float* d = dst + (size_t)r * F_HID + lane * 4;
    atomicAdd(d + 0, s.x * v);
    atomicAdd(d + 1, s.y * v);
    atomicAdd(d + 2, s.z * v);
    atomicAdd(d + 3, s.w * v);
}

// ---------------------------------------------------------------------------
// SpMM F=32: 8 lanes per edge (4 edges per warp).
// ---------------------------------------------------------------------------
__global__ void spmm_f32_kernel(const int* __restrict__ erow,
                                const int* __restrict__ ecol,
                                const float* __restrict__ eval,
                                const float* __restrict__ src,
                                float* __restrict__ dst, int E) {
    long long gid = (long long)blockIdx.x * blockDim.x + threadIdx.x;
    int e    = (int)(gid >> 3);
    int lane = (int)(gid & 7);
    if (e >= E) return;
    int r   = erow[e];
    int c   = ecol[e];
    float v = eval[e];
    float4 s = *(const float4*)(src + (size_t)c * F_OUT + lane * 4);
    float* d = dst + (size_t)r * F_OUT + lane * 4;
    atomicAdd(d + 0, s.x * v);
    atomicAdd(d + 1, s.y * v);
    atomicAdd(d + 2, s.z * v);
    atomicAdd(d + 3, s.w * v);
}

// ---------------------------------------------------------------------------
// GEMM2: T[M,32] = relu(H[M,128]) @ W2[128,32]. 8 rows per 256-thread block.
// ---------------------------------------------------------------------------
__global__ __launch_bounds__(256) void gemm2_kernel(const float* __restrict__ H,
                                                    const float* __restrict__ W2,
                                                    float* __restrict__ T, int M) {
    __shared__ float Ws[F_HID * F_OUT];  // 16 KB
    __shared__ float Hs[8][F_HID];       // 4 KB
    const int tid = threadIdx.x;
    for (int i = tid; i < F_HID * F_OUT; i += 256) Ws[i] = W2[i];

    const int row0 = blockIdx.x * 8;
    const int lr = tid >> 5;          // 0..7
    const int lc = (tid & 31) << 2;   // 0..124
    const int gr = row0 + lr;
    float4 hv = make_float4(0.f, 0.f, 0.f, 0.f);
    if (gr < M) hv = *(const float4*)(H + (size_t)gr * F_HID + lc);
    hv.x = fmaxf(hv.x, 0.f);
    hv.y = fmaxf(hv.y, 0.f);
    hv.z = fmaxf(hv.z, 0.f);
    hv.w = fmaxf(hv.w, 0.f);
    *(float4*)&Hs[lr][lc] = hv;
    __syncthreads();

    const int r = tid >> 5;   // row within block
    const int c = tid & 31;   // output column
    float s = 0.f;
#pragma unroll
    for (int k = 0; k < F_HID; k++)
        s = fmaf(Hs[r][k], Ws[k * F_OUT + c], s);
    int g = row0 + r;
    if (g < M) T[(size_t)g * F_OUT + c] = s;
}

// ---------------------------------------------------------------------------
// Row-wise log-softmax over 32 cols: one warp per row.
// ---------------------------------------------------------------------------
__global__ void logsoftmax_kernel(const float* __restrict__ L,
                                  float* __restrict__ out, int M) {
    long long gid = (long long)blockIdx.x * blockDim.x + threadIdx.x;
    int row  = (int)(gid >> 5);
    int lane = (int)(gid & 31);
    if (row >= M) return;
    float x = L[(size_t)row * 32 + lane];
    float m = x;
#pragma unroll
    for (int o = 16; o; o >>= 1) m = fmaxf(m, __shfl_xor_sync(0xffffffffu, m, o));
    float ex = expf(x - m);
    float s = ex;
#pragma unroll
    for (int o = 16; o; o >>= 1) s += __shfl_xor_sync(0xffffffffu, s, o);
    out[(size_t)row * 32 + lane] = x - m - logf(s);
}

// ---------------------------------------------------------------------------
extern "C" void kernel_launch(void* const* d_in, const int* in_sizes, int n_in,
                              void* d_out, int out_size) {
    const float* x    = (const float*)d_in[0];
    const int*   erow = (const int*)d_in[1];
    const int*   ecol = (const int*)d_in[2];
    const float* ev   = (const float*)d_in[3];
    const float* W1   = (const float*)d_in[4];
    const float* b1   = (const float*)d_in[5];
    const float* W2   = (const float*)d_in[6];
    const float* b2   = (const float*)d_in[7];
    float* out = (float*)d_out;

    const int M = in_sizes[0] / F_IN;   // 100000
    const int E = in_sizes[1];          // 3200000

    float *support, *h, *t, *logits;
    cudaGetSymbolAddress((void**)&support, g_support);
    cudaGetSymbolAddress((void**)&h,       g_h);
    cudaGetSymbolAddress((void**)&t,       g_t);
    cudaGetSymbolAddress((void**)&logits,  g_logits);

    // h <- broadcast(b1)   (scatter target init; bias fused for free)
    {
        int total = M * F_HID;
        init_bias_kernel<<<(total + 255) / 256, 256>>>(h, b1, F_HID - 1, total);
    }
    // support <- x @ W1
    gemm1_kernel<<<(M + 127) / 128, 256>>>(x, W1, support, M);
    // h += A @ support
    {
        long long thr = (long long)E * 32;
        spmm_f128_kernel<<<(unsigned)((thr + 255) / 256), 256>>>(erow, ecol, ev,
                                                                 support, h, E);
    }
    // logits <- broadcast(b2)
    {
        int total = M * F_OUT;
        init_bias_kernel<<<(total + 255) / 256, 256>>>(logits, b2, F_OUT - 1, total);
    }
    // t <- relu(h) @ W2
    gemm2_kernel<<<(M + 7) / 8, 256>>>(h, W2, t, M);
    // logits += A @ t
    {
        long long thr = (long long)E * 8;
        spmm_f32_kernel<<<(unsigned)((thr + 255) / 256), 256>>>(erow, ecol, ev,
                                                                t, logits, E);
    }
    // out <- log_softmax(logits)
    {
        long long thr = (long long)M * 32;
        logsoftmax_kernel<<<(unsigned)((thr + 255) / 256), 256>>>(logits, out, M);
    }
}

// round 2
// speedup vs baseline: 2.0372x; 2.0372x over previous
#include <cuda_runtime.h>
#include <math.h>

#define N_NODES_MAX 100000
#define E_MAX       3300000
#define F_IN  512
#define F_HID 128
#define F_OUT 32

// Scratch (allocation-free rule: __device__ globals)
__device__ float g_support[(size_t)N_NODES_MAX * F_HID];  // x @ W1
__device__ float g_t[(size_t)N_NODES_MAX * F_OUT];        // relu(h) @ W2
__device__ int   g_rowptr[N_NODES_MAX + 1];
__device__ int   g_deg[N_NODES_MAX];
__device__ int   g_cursor[N_NODES_MAX];
__device__ int   g_ecol[E_MAX];
__device__ float g_eval[E_MAX];

// ---------------------------------------------------------------------------
// CSR build step 1: zero degree counters
// ---------------------------------------------------------------------------
__global__ void zero_deg_kernel(int* __restrict__ deg, int n) {
    int i = blockIdx.x * blockDim.x + threadIdx.x;
    if (i < n) deg[i] = 0;
}

// CSR build step 2: histogram of edge rows
__global__ void hist_kernel(const int* __restrict__ erow, int* __restrict__ deg,
                            int E) {
    int e = blockIdx.x * blockDim.x + threadIdx.x;
    if (e < E) atomicAdd(&deg[erow[e]], 1);
}

// CSR build step 3: single-block inclusive scan (warp-scan based), also fills
// cursor[i] = rowptr[i] (exclusive prefix) for the scatter pass.
__global__ __launch_bounds__(1024) void scan_kernel(const int* __restrict__ deg,
                                                    int* __restrict__ rowptr,
                                                    int* __restrict__ cursor,
                                                    int n) {
    __shared__ int wsum[32];
    __shared__ int carry_s;
    const int tid  = threadIdx.x;
    const int lane = tid & 31;
    const int wid  = tid >> 5;
    if (tid == 0) { carry_s = 0; rowptr[0] = 0; }
    __syncthreads();

    for (int base = 0; base < n; base += 1024) {
        int i = base + tid;
        int v = (i < n) ? deg[i] : 0;
        int x = v;
#pragma unroll
        for (int o = 1; o < 32; o <<= 1) {
            int t = __shfl_up_sync(0xffffffffu, x, o);
            if (lane >= o) x += t;
        }
        if (lane == 31) wsum[wid] = x;
        __syncthreads();
        if (wid == 0) {
            int w = wsum[lane];
#pragma unroll
            for (int o = 1; o < 32; o <<= 1) {
                int t = __shfl_up_sync(0xffffffffu, w, o);
                if (lane >= o) w += t;
            }
            wsum[lane] = w;
        }
        __syncthreads();
        int inc = x + (wid > 0 ? wsum[wid - 1] : 0) + carry_s;
        if (i < n) { rowptr[i + 1] = inc; cursor[i] = inc - v; }
        __syncthreads();
        if (tid == 1023) carry_s = inc;
        __syncthreads();
    }
}

// CSR build step 4: scatter edges into row-sorted order
__global__ void scatter_kernel(const int* __restrict__ erow,
                               const int* __restrict__ ecol,
                               const float* __restrict__ ev,
                               int* __restrict__ cursor,
                               int* __restrict__ ecol_s,
                               float* __restrict__ eval_s, int E) {
    int e = blockIdx.x * blockDim.x + threadIdx.x;
    if (e >= E) return;
    int r = erow[e];
    int pos = atomicAdd(&cursor[r], 1);
    ecol_s[pos] = ecol[e];
    eval_s[pos] = ev[e];
}

// ---------------------------------------------------------------------------
// GEMM1: C[M,128] = A[M,512] @ B[512,128], fp32.
// 128x128 block tile, BK=8, 256 threads, 8x8 register tile per thread.
// ---------------------------------------------------------------------------
__global__ __launch_bounds__(256) void gemm1_kernel(const float* __restrict__ A,
                                                    const float* __restrict__ B,
                                                    float* __restrict__ C,
                                                    int M) {
    __shared__ float As[8][128];
    __shared__ float Bs[8][128];
    const int tid  = threadIdx.x;
    const int row0 = blockIdx.x * 128;
    const int tr = (tid >> 4) << 3;
    const int tc = (tid & 15) << 3;

    float acc[8][8];
#pragma unroll
    for (int i = 0; i < 8; i++)
#pragma unroll
        for (int j = 0; j < 8; j++) acc[i][j] = 0.f;

    const int a_row = tid >> 1;
    const int a_col = (tid & 1) << 2;
    const int b_row = tid >> 5;
    const int b_col = (tid & 31) << 2;
    const int grow  = row0 + a_row;
    const bool aok  = (grow < M);
    const float* Ap = A + (size_t)grow * F_IN + a_col;

    for (int k0 = 0; k0 < F_IN; k0 += 8) {
        float4 av = make_float4(0.f, 0.f, 0.f, 0.f);
        if (aok) av = *(const float4*)(Ap + k0);
        float4 bv = *(const float4*)(B + (size_t)(k0 + b_row) * F_HID + b_col);

        __syncthreads();
        As[a_col + 0][a_row] = av.x;
        As[a_col + 1][a_row] = av.y;
        As[a_col + 2][a_row] = av.z;
        As[a_col + 3][a_row] = av.w;
        *(float4*)&Bs[b_row][b_col] = bv;
        __syncthreads();

#pragma unroll
        for (int k = 0; k < 8; k++) {
            float ar[8], br[8];
            *(float4*)&ar[0] = *(const float4*)&As[k][tr];
            *(float4*)&ar[4] = *(const float4*)&As[k][tr + 4];
            *(float4*)&br[0] = *(const float4*)&Bs[k][tc];
            *(float4*)&br[4] = *(const float4*)&Bs[k][tc + 4];
#pragma unroll
            for (int i = 0; i < 8; i++)
#pragma unroll
                for (int j = 0; j < 8; j++)
                    acc[i][j] = fmaf(ar[i], br[j], acc[i][j]);
        }
    }

#pragma unroll
    for (int i = 0; i < 8; i++) {
        int r = row0 + tr + i;
        if (r < M) {
            *(float4*)&C[(size_t)r * F_HID + tc] =
                make_float4(acc[i][0], acc[i][1], acc[i][2], acc[i][3]);
            *(float4*)&C[(size_t)r * F_HID + tc + 4] =
                make_float4(acc[i][4], acc[i][5], acc[i][6], acc[i][7]);
        }
    }
}

// ---------------------------------------------------------------------------
// Fused: h_row = sum_e val*support[col] + b1 ; relu ; t_row = h_row @ W2.
// One warp per node row; 8 warps per block; W2 staged in smem.
// Lane holds h features [lane*4 .. lane*4+3].
// ---------------------------------------------------------------------------
__global__ __launch_bounds__(256) void spmm1_gemm2_kernel(
    const int* __restrict__ rowptr, const int* __restrict__ ecol_s,
    const float* __restrict__ eval_s, const float* __restrict__ support,
    const float* __restrict__ b1, const float* __restrict__ W2,
    float* __restrict__ T, int M) {
    __shared__ float Ws[F_HID * F_OUT];  // 16 KB, [k*32 + j]
    const int tid = threadIdx.x;
    for (int i = tid; i < F_HID * F_OUT; i += 256) Ws[i] = W2[i];
    __syncthreads();

    const int lane = tid & 31;
    const int wid  = tid >> 5;
    const int row  = blockIdx.x * 8 + wid;
    if (row >= M) return;

    float4 hb = *(const float4*)(b1 + lane * 4);
    float h0 = hb.x, h1 = hb.y, h2 = hb.z, h3 = hb.w;

    const int start = rowptr[row];
    const int end   = rowptr[row + 1];
    for (int base = start; base < end; base += 32) {
        int idx = base + lane;
        int cnt = min(32, end - base);
        int   c = (idx < end) ? ecol_s[idx] : 0;
        float v = (idx < end) ? eval_s[idx] : 0.f;
        for (int j = 0; j < cnt; j++) {
            int   cc = __shfl_sync(0xffffffffu, c, j);
            float vv = __shfl_sync(0xffffffffu, v, j);
            float4 s = *(const float4*)(support + (size_t)cc * F_HID + lane * 4);
            h0 = fmaf(s.x, vv, h0);
            h1 = fmaf(s.y, vv, h1);
            h2 = fmaf(s.z, vv, h2);
            h3 = fmaf(s.w, vv, h3);
        }
    }
    // ReLU
    h0 = fmaxf(h0, 0.f); h1 = fmaxf(h1, 0.f);
    h2 = fmaxf(h2, 0.f); h3 = fmaxf(h3, 0.f);

    // GEMM2 within the warp: t[j=lane] = sum_k relu_h[k] * W2[k][lane]
    float tacc = 0.f;
#pragma unroll 8
    for (int l = 0; l < 32; l++) {
        float a0 = __shfl_sync(0xffffffffu, h0, l);
        float a1 = __shfl_sync(0xffffffffu, h1, l);
        float a2 = __shfl_sync(0xffffffffu, h2, l);
        float a3 = __shfl_sync(0xffffffffu, h3, l);
        int k = l * 4;
        tacc = fmaf(a0, Ws[(k + 0) * F_OUT + lane], tacc);
        tacc = fmaf(a1, Ws[(k + 1) * F_OUT + lane], tacc);
        tacc = fmaf(a2, Ws[(k + 2) * F_OUT + lane], tacc);
        tacc = fmaf(a3, Ws[(k + 3) * F_OUT + lane], tacc);
    }
    T[(size_t)row * F_OUT + lane] = tacc;
}

// ---------------------------------------------------------------------------
// Fused: logits_row = sum_e val*t[col] + b2 ; log_softmax ; write out.
// One warp per node row.
// ---------------------------------------------------------------------------
__global__ __launch_bounds__(256) void spmm2_lsm_kernel(
    const int* __restrict__ rowptr, const int* __restrict__ ecol_s,
    const float* __restrict__ eval_s, const float* __restrict__ T,
    const float* __restrict__ b2, float* __restrict__ out, int M) {
    const int tid  = threadIdx.x;
    const int lane = tid & 31;
    const int wid  = tid >> 5;
    const int row  = blockIdx.x * 8 + wid;
    if (row >= M) return;

    float acc = b2[lane];
    const int start = rowptr[row];
    const int end   = rowptr[row + 1];
    for (int base = start; base < end; base += 32) {
        int idx = base + lane;
        int cnt = min(32, end - base);
        int   c = (idx < end) ? ecol_s[idx] : 0;
        float v = (idx < end) ? eval_s[idx] : 0.f;
        for (int j = 0; j < cnt; j++) {
            int   cc = __shfl_sync(0xffffffffu, c, j);
            float vv = __shfl_sync(0xffffffffu, v, j);
            acc = fmaf(__ldg(T + (size_t)cc * F_OUT + lane), vv, acc);
        }
    }
    // log-softmax over the 32 lanes
    float m = acc;
#pragma unroll
    for (int o = 16; o; o >>= 1) m = fmaxf(m, __shfl_xor_sync(0xffffffffu, m, o));
    float ex = expf(acc - m);
    float s = ex;
#pragma unroll
    for (int o = 16; o; o >>= 1) s += __shfl_xor_sync(0xffffffffu, s, o);
    out[(size_t)row * F_OUT + lane] = acc - m - logf(s);
}

// ---------------------------------------------------------------------------
extern "C" void kernel_launch(void* const* d_in, const int* in_sizes, int n_in,
                              void* d_out, int out_size) {
    const float* x    = (const float*)d_in[0];
    const int*   erow = (const int*)d_in[1];
    const int*   ecol = (const int*)d_in[2];
    const float* ev   = (const float*)d_in[3];
    const float* W1   = (const float*)d_in[4];
    const float* b1   = (const float*)d_in[5];
    const float* W2   = (const float*)d_in[6];
    const float* b2   = (const float*)d_in[7];
    float* out = (float*)d_out;

    const int M = in_sizes[0] / F_IN;   // 100000
    const int E = in_sizes[1];          // 3200000

    float *support, *t, *evs;
    int *rowptr, *deg, *cursor, *ecs;
    cudaGetSymbolAddress((void**)&support, g_support);
    cudaGetSymbolAddress((void**)&t,       g_t);
    cudaGetSymbolAddress((void**)&rowptr,  g_rowptr);
    cudaGetSymbolAddress((void**)&deg,     g_deg);
    cudaGetSymbolAddress((void**)&cursor,  g_cursor);
    cudaGetSymbolAddress((void**)&ecs,     g_ecol);
    cudaGetSymbolAddress((void**)&evs,     g_eval);

    // --- CSR build ---
    zero_deg_kernel<<<(M + 255) / 256, 256>>>(deg, M);
    hist_kernel<<<(E + 255) / 256, 256>>>(erow, deg, E);
    scan_kernel<<<1, 1024>>>(deg, rowptr, cursor, M);
    scatter_kernel<<<(E + 255) / 256, 256>>>(erow, ecol, ev, cursor, ecs, evs, E);

    // --- support = x @ W1 ---
    gemm1_kernel<<<(M + 127) / 128, 256>>>(x, W1, support, M);

    // --- t = relu(A @ support + b1) @ W2 ---
    spmm1_gemm2_kernel<<<(M + 7) / 8, 256>>>(rowptr, ecs, evs, support, b1, W2,
                                             t, M);

    // --- out = log_softmax(A @ t + b2) ---
    spmm2_lsm_kernel<<<(M + 7) / 8, 256>>>(rowptr, ecs, evs, t, b2, out, M);
}

// round 3
// speedup vs baseline: 2.1088x; 1.0351x over previous
#include <cuda_runtime.h>
#include <cuda_bf16.h>
#include <math.h>

#define N_NODES_MAX 100000
#define E_MAX       3300000
#define F_IN  512
#define F_HID 128
#define F_OUT 32

// Scratch (allocation-free rule: __device__ globals)
__device__ float g_support[(size_t)N_NODES_MAX * F_HID];  // x @ W1
__device__ float g_t[(size_t)N_NODES_MAX * F_OUT];        // relu(h) @ W2
__device__ int   g_rowptr[N_NODES_MAX + 1];
__device__ int   g_deg[N_NODES_MAX];
__device__ int   g_cursor[N_NODES_MAX];
__device__ int   g_bsum[256];
__device__ int   g_ecol[E_MAX];
__device__ float g_eval[E_MAX];

// ---------------------------------------------------------------------------
// CSR build
// ---------------------------------------------------------------------------
__global__ void zero_deg_kernel(int* __restrict__ deg, int n) {
    int i = blockIdx.x * blockDim.x + threadIdx.x;
    if (i < n) deg[i] = 0;
}

__global__ void hist_kernel(const int* __restrict__ erow, int* __restrict__ deg,
                            int E) {
    int e = blockIdx.x * blockDim.x + threadIdx.x;
    if (e < E) atomicAdd(&deg[erow[e]], 1);
}

// Phase A: per-block (1024-wide) inclusive scan; rowptr[i+1] <- local inclusive,
// bsum[blk] <- block total.
__global__ __launch_bounds__(1024) void scanA_kernel(const int* __restrict__ deg,
                                                     int* __restrict__ rowptr,
                                                     int* __restrict__ bsum,
                                                     int n) {
    __shared__ int wsum[32];
    const int tid  = threadIdx.x;
    const int lane = tid & 31;
    const int wid  = tid >> 5;
    int i = blockIdx.x * 1024 + tid;
    int v = (i < n) ? deg[i] : 0;
    int x = v;
#pragma unroll
    for (int o = 1; o < 32; o <<= 1) {
        int t = __shfl_up_sync(0xffffffffu, x, o);
        if (lane >= o) x += t;
    }
    if (lane == 31) wsum[wid] = x;
    __syncthreads();
    if (wid == 0) {
        int w = wsum[lane];
#pragma unroll
        for (int o = 1; o < 32; o <<= 1) {
            int t = __shfl_up_sync(0xffffffffu, w, o);
            if (lane >= o) w += t;
        }
        wsum[lane] = w;
    }
    __syncthreads();
    int inc = x + (wid > 0 ? wsum[wid - 1] : 0);
    if (i < n) rowptr[i + 1] = inc;
    if (tid == 1023) bsum[blockIdx.x] = inc;
}

// Phase B: exclusive scan of block sums (<=256 blocks), one block of 256.
__global__ __launch_bounds__(256) void scanB_kernel(int* __restrict__ bsum,
                                                    int nblk) {
    __shared__ int wsum[8];
    const int tid  = threadIdx.x;
    const int lane = tid & 31;
    const int wid  = tid >> 5;
    int v = (tid < nblk) ? bsum[tid] : 0;
    int x = v;
#pragma unroll
    for (int o = 1; o < 32; o <<= 1) {
        int t = __shfl_up_sync(0xffffffffu, x, o);
        if (lane >= o) x += t;
    }
    if (lane == 31) wsum[wid] = x;
    __syncthreads();
    if (wid == 0 && lane < 8) {
        int w = wsum[lane];
#pragma unroll
        for (int o = 1; o < 8; o <<= 1) {
            int t = __shfl_up_sync(0xffu, w, o);
            if (lane >= o) w += t;
        }
        wsum[lane] = w;
    }
    __syncthreads();
    int inc = x + (wid > 0 ? wsum[wid - 1] : 0);
    if (tid < nblk) bsum[tid] = inc - v;  // exclusive
}

// Phase C: add block offsets, produce final rowptr and cursor.
__global__ void scanC_kernel(const int* __restrict__ deg,
                             int* __restrict__ rowptr,
                             const int* __restrict__ bsum,
                             int* __restrict__ cursor, int n) {
    int i = blockIdx.x * blockDim.x + threadIdx.x;
    if (i >= n) return;
    int inc = rowptr[i + 1] + bsum[i >> 10];
    rowptr[i + 1] = inc;
    cursor[i] = inc - deg[i];
    if (i == 0) rowptr[0] = 0;
}

__global__ void scatter_kernel(const int* __restrict__ erow,
                               const int* __restrict__ ecol,
                               const float* __restrict__ ev,
                               int* __restrict__ cursor,
                               int* __restrict__ ecol_s,
                               float* __restrict__ eval_s, int E) {
    int e = blockIdx.x * blockDim.x + threadIdx.x;
    if (e >= E) return;
    int r = erow[e];
    int pos = atomicAdd(&cursor[r], 1);
    ecol_s[pos] = ecol[e];
    eval_s[pos] = ev[e];
}

// ---------------------------------------------------------------------------
// GEMM1 on tensor cores: C[M,128] = A[M,512] @ W1[512,128], fp32 in/out.
// bf16 two-way split (hi+lo), 3 mma products -> ~1e-5 accuracy.
// CTA: 128 rows x 128 cols, 256 threads (8 warps; warp w owns rows 16w..16w+15).
// K chunked by 16 (one m16n8k16 k-step per chunk).
// ---------------------------------------------------------------------------
#define SMS 24  // padded k-stride (bf16 elems) for conflict-free frag loads

__device__ __forceinline__ void mma16816(float& d0, float& d1, float& d2, float& d3,
                                         unsigned a0, unsigned a1, unsigned a2,
                                         unsigned a3, unsigned b0, unsigned b1) {
    asm volatile(
        "mma.sync.aligned.m16n8k16.row.col.f32.bf16.bf16.f32 "
        "{%0,%1,%2,%3}, {%4,%5,%6,%7}, {%8,%9}, {%0,%1,%2,%3};"
        : "+f"(d0), "+f"(d1), "+f"(d2), "+f"(d3)
        : "r"(a0), "r"(a1), "r"(a2), "r"(a3), "r"(b0), "r"(b1));
}

__global__ __launch_bounds__(256, 2) void gemm1_mma_kernel(
    const float* __restrict__ A, const float* __restrict__ W1,
    float* __restrict__ C, int M) {
    __shared__ __nv_bfloat16 As_hi[128 * SMS];
    __shared__ __nv_bfloat16 As_lo[128 * SMS];
    __shared__ __nv_bfloat16 Bt_hi[128 * SMS];  // [n][k]
    __shared__ __nv_bfloat16 Bt_lo[128 * SMS];

    const int tid  = threadIdx.x;
    const int lane = tid & 31;
    const int wid  = tid >> 5;
    const int g    = lane >> 2;   // groupID 0..7
    const int tg   = lane & 3;    // thread-in-group
    const int row0 = blockIdx.x * 128;

    float acc[16][4];
#pragma unroll
    for (int i = 0; i < 16; i++)
#pragma unroll
        for (int j = 0; j < 4; j++) acc[i][j] = 0.f;

    // A-load mapping: thread -> (row = tid>>1, 8 cols at (tid&1)*8)
    const int ar   = tid >> 1;
    const int ac   = (tid & 1) * 8;
    const bool aok = (row0 + ar) < M;
    const float* Ap = A + (size_t)(row0 + ar) * F_IN + ac;
    // B-load mapping: thread -> (k = tid>>4, 8 cols at (tid&15)*8)
    const int bk = tid >> 4;
    const int bn = (tid & 15) * 8;
    const float* Bp = W1 + (size_t)bk * F_HID + bn;

    for (int k0 = 0; k0 < F_IN; k0 += 16) {
        // --- load + split A chunk [128 x 16] ---
        float4 av0 = make_float4(0.f, 0.f, 0.f, 0.f), av1 = av0;
        if (aok) {
            av0 = *(const float4*)(Ap + k0);
            av1 = *(const float4*)(Ap + k0 + 4);
        }
        // --- load + split B chunk [16 x 128] ---
        float4 bv0 = *(const float4*)(Bp + (size_t)k0 * F_HID);
        float4 bv1 = *(const float4*)(Bp + (size_t)k0 * F_HID + 4);

        __syncthreads();
        {
            const float a8[8] = {av0.x, av0.y, av0.z, av0.w,
                                 av1.x, av1.y, av1.z, av1.w};
            __nv_bfloat16* dh = As_hi + ar * SMS + ac;
            __nv_bfloat16* dl = As_lo + ar * SMS + ac;
#pragma unroll
            for (int j = 0; j < 8; j++) {
                __nv_bfloat16 h = __float2bfloat16(a8[j]);
                dh[j] = h;
                dl[j] = __float2bfloat16(a8[j] - __bfloat162float(h));
            }
            const float b8[8] = {bv0.x, bv0.y, bv0.z, bv0.w,
                                 bv1.x, bv1.y, bv1.z, bv1.w};
#pragma unroll
            for (int j = 0; j < 8; j++) {
                __nv_bfloat16 h = __float2bfloat16(b8[j]);
                Bt_hi[(bn + j) * SMS + bk] = h;
                Bt_lo[(bn + j) * SMS + bk] =
                    __float2bfloat16(b8[j] - __bfloat162float(h));
            }
        }
        __syncthreads();

        // --- A fragments for this warp's 16 rows ---
        const int arow = wid * 16 + g;
        unsigned ah0 = *(const unsigned*)&As_hi[arow * SMS + 2 * tg];
        unsigned ah1 = *(const unsigned*)&As_hi[(arow + 8) * SMS + 2 * tg];
        unsigned ah2 = *(const unsigned*)&As_hi[arow * SMS + 2 * tg + 8];
        unsigned ah3 = *(const unsigned*)&As_hi[(arow + 8) * SMS + 2 * tg + 8];
        unsigned al0 = *(const unsigned*)&As_lo[arow * SMS + 2 * tg];
        unsigned al1 = *(const unsigned*)&As_lo[(arow + 8) * SMS + 2 * tg];
        unsigned al2 = *(const unsigned*)&As_lo[arow * SMS + 2 * tg + 8];
        unsigned al3 = *(const unsigned*)&As_lo[(arow + 8) * SMS + 2 * tg + 8];

#pragma unroll
        for (int nt = 0; nt < 16; nt++) {
            const int n = nt * 8 + g;
            unsigned bh0 = *(const unsigned*)&Bt_hi[n * SMS + 2 * tg];
            unsigned bh1 = *(const unsigned*)&Bt_hi[n * SMS + 2 * tg + 8];
            unsigned bl0 = *(const unsigned*)&Bt_lo[n * SMS + 2 * tg];
            unsigned bl1 = *(const unsigned*)&Bt_lo[n * SMS + 2 * tg + 8];
            mma16816(acc[nt][0], acc[nt][1], acc[nt][2], acc[nt][3],
                     ah0, ah1, ah2, ah3, bh0, bh1);
            mma16816(acc[nt][0], acc[nt][1], acc[nt][2], acc[nt][3],
                     ah0, ah1, ah2, ah3, bl0, bl1);
            mma16816(acc[nt][0], acc[nt][1], acc[nt][2], acc[nt][3],
                     al0, al1, al2, al3, bh0, bh1);
        }
    }

    // --- epilogue ---
    const int r0 = row0 + wid * 16 + g;
    const int r1 = r0 + 8;
#pragma unroll
    for (int nt = 0; nt < 16; nt++) {
        const int col = nt * 8 + 2 * tg;
        if (r0 < M)
            *(float2*)&C[(size_t)r0 * F_HID + col] =
                make_float2(acc[nt][0], acc[nt][1]);
        if (r1 < M)
            *(float2*)&C[(size_t)r1 * F_HID + col] =
                make_float2(acc[nt][2], acc[nt][3]);
    }
}

// ---------------------------------------------------------------------------
// Fused: h_row = sum_e val*support[col] + b1 ; relu ; t_row = h_row @ W2.
// One warp per node row; 8 warps per block; W2 staged in smem.
// ---------------------------------------------------------------------------
__global__ __launch_bounds__(256) void spmm1_gemm2_kernel(
    const int* __restrict__ rowptr, const int* __restrict__ ecol_s,
    const float* __restrict__ eval_s, const float* __restrict__ support,
    const float* __restrict__ b1, const float* __restrict__ W2,
    float* __restrict__ T, int M) {
    __shared__ float Ws[F_HID * F_OUT];  // 16 KB, [k*32 + j]
    const int tid = threadIdx.x;
    for (int i = tid; i < F_HID * F_OUT; i += 256) Ws[i] = W2[i];
    __syncthreads();

    const int lane = tid & 31;
    const int wid  = tid >> 5;
    const int row  = blockIdx.x * 8 + wid;
    if (row >= M) return;

    float4 hb = *(const float4*)(b1 + lane * 4);
    float h0 = hb.x, h1 = hb.y, h2 = hb.z, h3 = hb.w;

    const int start = rowptr[row];
    const int end   = rowptr[row + 1];
    for (int base = start; base < end; base += 32) {
        int idx = base + lane;
        int cnt = min(32, end - base);
        int   c = (idx < end) ? ecol_s[idx] : 0;
        float v = (idx < end) ? eval_s[idx] : 0.f;
        for (int j = 0; j < cnt; j++) {
            int   cc = __shfl_sync(0xffffffffu, c, j);
            float vv = __shfl_sync(0xffffffffu, v, j);
            float4 s = *(const float4*)(support + (size_t)cc * F_HID + lane * 4);
            h0 = fmaf(s.x, vv, h0);
            h1 = fmaf(s.y, vv, h1);
            h2 = fmaf(s.z, vv, h2);
            h3 = fmaf(s.w, vv, h3);
        }
    }
    h0 = fmaxf(h0, 0.f); h1 = fmaxf(h1, 0.f);
    h2 = fmaxf(h2, 0.f); h3 = fmaxf(h3, 0.f);

    float tacc = 0.f;
#pragma unroll 8
    for (int l = 0; l < 32; l++) {
        float a0 = __shfl_sync(0xffffffffu, h0, l);
        float a1 = __shfl_sync(0xffffffffu, h1, l);
        float a2 = __shfl_sync(0xffffffffu, h2, l);
        float a3 = __shfl_sync(0xffffffffu, h3, l);
        int k = l * 4;
        tacc = fmaf(a0, Ws[(k + 0) * F_OUT + lane], tacc);
        tacc = fmaf(a1, Ws[(k + 1) * F_OUT + lane], tacc);
        tacc = fmaf(a2, Ws[(k + 2) * F_OUT + lane], tacc);
        tacc = fmaf(a3, Ws[(k + 3) * F_OUT + lane], tacc);
    }
    T[(size_t)row * F_OUT + lane] = tacc;
}

// ---------------------------------------------------------------------------
// Fused: logits_row = sum_e val*t[col] + b2 ; log_softmax ; write out.
// ---------------------------------------------------------------------------
__global__ __launch_bounds__(256) void spmm2_lsm_kernel(
    const int* __restrict__ rowptr, const int* __restrict__ ecol_s,
    const float* __restrict__ eval_s, const float* __restrict__ T,
    const float* __restrict__ b2, float* __restrict__ out, int M) {
    const int tid  = threadIdx.x;
    const int lane = tid & 31;
    const int wid  = tid >> 5;
    const int row  = blockIdx.x * 8 + wid;
    if (row >= M) return;

    float acc = b2[lane];
    const int start = rowptr[row];
    const int end   = rowptr[row + 1];
    for (int base = start; base < end; base += 32) {
        int idx = base + lane;
        int cnt = min(32, end - base);
        int   c = (idx < end) ? ecol_s[idx] : 0;
        float v = (idx < end) ? eval_s[idx] : 0.f;
        for (int j = 0; j < cnt; j++) {
            int   cc = __shfl_sync(0xffffffffu, c, j);
            float vv = __shfl_sync(0xffffffffu, v, j);
            acc = fmaf(__ldg(T + (size_t)cc * F_OUT + lane), vv, acc);
        }
    }
    float m = acc;
#pragma unroll
    for (int o = 16; o; o >>= 1) m = fmaxf(m, __shfl_xor_sync(0xffffffffu, m, o));
    float ex = expf(acc - m);
    float s = ex;
#pragma unroll
    for (int o = 16; o; o >>= 1) s += __shfl_xor_sync(0xffffffffu, s, o);
    out[(size_t)row * F_OUT + lane] = acc - m - logf(s);
}

// ---------------------------------------------------------------------------
extern "C" void kernel_launch(void* const* d_in, const int* in_sizes, int n_in,
                              void* d_out, int out_size) {
    const float* x    = (const float*)d_in[0];
    const int*   erow = (const int*)d_in[1];
    const int*   ecol = (const int*)d_in[2];
    const float* ev   = (const float*)d_in[3];
    const float* W1   = (const float*)d_in[4];
    const float* b1   = (const float*)d_in[5];
    const float* W2   = (const float*)d_in[6];
    const float* b2   = (const float*)d_in[7];
    float* out = (float*)d_out;

    const int M = in_sizes[0] / F_IN;   // 100000
    const int E = in_sizes[1];          // 3200000

    float *support, *t, *evs;
    int *rowptr, *deg, *cursor, *ecs, *bsum;
    cudaGetSymbolAddress((void**)&support, g_support);
    cudaGetSymbolAddress((void**)&t,       g_t);
    cudaGetSymbolAddress((void**)&rowptr,  g_rowptr);
    cudaGetSymbolAddress((void**)&deg,     g_deg);
    cudaGetSymbolAddress((void**)&cursor,  g_cursor);
    cudaGetSymbolAddress((void**)&bsum,    g_bsum);
    cudaGetSymbolAddress((void**)&ecs,     g_ecol);
    cudaGetSymbolAddress((void**)&evs,     g_eval);

    const int nblk = (M + 1023) / 1024;

    // --- CSR build ---
    zero_deg_kernel<<<(M + 255) / 256, 256>>>(deg, M);
    hist_kernel<<<(E + 255) / 256, 256>>>(erow, deg, E);
    scanA_kernel<<<nblk, 1024>>>(deg, rowptr, bsum, M);
    scanB_kernel<<<1, 256>>>(bsum, nblk);
    scanC_kernel<<<(M + 255) / 256, 256>>>(deg, rowptr, bsum, cursor, M);
    scatter_kernel<<<(E + 255) / 256, 256>>>(erow, ecol, ev, cursor, ecs, evs, E);

    // --- support = x @ W1 (tensor cores, bf16 split) ---
    gemm1_mma_kernel<<<(M + 127) / 128, 256>>>(x, W1, support, M);

    // --- t = relu(A @ support + b1) @ W2 ---
    spmm1_gemm2_kernel<<<(M + 7) / 8, 256>>>(rowptr, ecs, evs, support, b1, W2,
                                             t, M);

    // --- out = log_softmax(A @ t + b2) ---
    spmm2_lsm_kernel<<<(M + 7) / 8, 256>>>(rowptr, ecs, evs, t, b2, out, M);
}

// round 5
// speedup vs baseline: 2.9963x; 1.4209x over previous
#include <cuda_runtime.h>
#include <cuda_fp16.h>
#include <math.h>
#include <stdint.h>

#define N_NODES_MAX 100000
#define E_MAX       3300000
#define F_IN  512
#define F_HID 128
#define F_OUT 32

// Scratch (allocation-free rule: __device__ globals)
__device__ __half   g_support[(size_t)N_NODES_MAX * F_HID];  // x @ W1 (fp16)
__device__ float    g_t[(size_t)N_NODES_MAX * F_OUT];        // relu(h) @ W2
__device__ uint32_t g_w1t[F_IN * F_HID];  // W1^T as tf32 bits, [n][k]
__device__ int      g_rowptr[N_NODES_MAX + 1];
__device__ int      g_deg[N_NODES_MAX];
__device__ int      g_cursor[N_NODES_MAX];
__device__ int      g_bsum[256];
__device__ int      g_ecol[E_MAX];
__device__ float    g_eval[E_MAX];

__device__ __forceinline__ uint32_t f2tf32(float f) {
    uint32_t r;
    asm("cvt.rna.tf32.f32 %0, %1;" : "=r"(r) : "f"(f));
    return r;
}

// ---------------------------------------------------------------------------
// CSR build
// ---------------------------------------------------------------------------
__global__ void hist_kernel(const int* __restrict__ erow, int* __restrict__ deg,
                            int E) {
    int e = blockIdx.x * blockDim.x + threadIdx.x;
    if (e < E) atomicAdd(&deg[erow[e]], 1);
}

__global__ __launch_bounds__(1024) void scanA_kernel(const int* __restrict__ deg,
                                                     int* __restrict__ rowptr,
                                                     int* __restrict__ bsum,
                                                     int n) {
    __shared__ int wsum[32];
    const int tid  = threadIdx.x;
    const int lane = tid & 31;
    const int wid  = tid >> 5;
    int i = blockIdx.x * 1024 + tid;
    int v = (i < n) ? deg[i] : 0;
    int x = v;
#pragma unroll
    for (int o = 1; o < 32; o <<= 1) {
        int t = __shfl_up_sync(0xffffffffu, x, o);
        if (lane >= o) x += t;
    }
    if (lane == 31) wsum[wid] = x;
    __syncthreads();
    if (wid == 0) {
        int w = wsum[lane];
#pragma unroll
        for (int o = 1; o < 32; o <<= 1) {
            int t = __shfl_up_sync(0xffffffffu, w, o);
            if (lane >= o) w += t;
        }
        wsum[lane] = w;
    }
    __syncthreads();
    int inc = x + (wid > 0 ? wsum[wid - 1] : 0);
    if (i < n) rowptr[i + 1] = inc;
    if (tid == 1023) bsum[blockIdx.x] = inc;
}

__global__ __launch_bounds__(256) void scanB_kernel(int* __restrict__ bsum,
                                                    int nblk) {
    __shared__ int wsum[8];
    const int tid  = threadIdx.x;
    const int lane = tid & 31;
    const int wid  = tid >> 5;
    int v = (tid < nblk) ? bsum[tid] : 0;
    int x = v;
#pragma unroll
    for (int o = 1; o < 32; o <<= 1) {
        int t = __shfl_up_sync(0xffffffffu, x, o);
        if (lane >= o) x += t;
    }
    if (lane == 31) wsum[wid] = x;
    __syncthreads();
    if (wid == 0 && lane < 8) {
        int w = wsum[lane];
#pragma unroll
        for (int o = 1; o < 8; o <<= 1) {
            int t = __shfl_up_sync(0xffu, w, o);
            if (lane >= o) w += t;
        }
        wsum[lane] = w;
    }
    __syncthreads();
    int inc = x + (wid > 0 ? wsum[wid - 1] : 0);
    if (tid < nblk) bsum[tid] = inc - v;
}

// Phase C: finalize rowptr/cursor; also convert+transpose W1 -> tf32 bits.
__global__ void scanC_kernel(const int* __restrict__ deg,
                             int* __restrict__ rowptr,
                             const int* __restrict__ bsum,
                             int* __restrict__ cursor,
                             const float* __restrict__ W1,
                             uint32_t* __restrict__ w1t, int n) {
    int i = blockIdx.x * blockDim.x + threadIdx.x;
    if (i < F_IN * F_HID) {
        int k  = i >> 7;        // W1 row
        int nn = i & 127;       // W1 col
        w1t[nn * F_IN + k] = f2tf32(W1[i]);
    }
    if (i >= n) return;
    int inc = rowptr[i + 1] + bsum[i >> 10];
    rowptr[i + 1] = inc;
    cursor[i] = inc - deg[i];
    if (i == 0) rowptr[0] = 0;
}

__global__ void scatter_kernel(const int* __restrict__ erow,
                               const int* __restrict__ ecol,
                               const float* __restrict__ ev,
                               int* __restrict__ cursor,
                               int* __restrict__ ecol_s,
                               float* __restrict__ eval_s, int E) {
    int e = blockIdx.x * blockDim.x + threadIdx.x;
    if (e >= E) return;
    int r = erow[e];
    int pos = atomicAdd(&cursor[r], 1);
    ecol_s[pos] = ecol[e];
    eval_s[pos] = ev[e];
}

// ---------------------------------------------------------------------------
// GEMM1: S[M,128] = tf32(A[M,512]) @ tf32(W1) -> fp16 out.
// 128x128 CTA tile, 256 threads (8 warps x 16 rows), k staged 64/chunk.
// mma.sync.m16n8k8.tf32.  smem stride 68 words (bank-conflict-free frags).
// ---------------------------------------------------------------------------
#define G1_STRIDE 68
#define G1_SMEM_BYTES (2 * 128 * G1_STRIDE * 4)

extern __shared__ uint32_t g1smem[];

__global__ __launch_bounds__(256, 2) void gemm1_tf32_kernel(
    const float* __restrict__ A, const uint32_t* __restrict__ Wt,
    __half* __restrict__ S, int M) {
    uint32_t* As = g1smem;                       // [128][68]
    uint32_t* Bs = g1smem + 128 * G1_STRIDE;     // [128][68]
    const int tid  = threadIdx.x;
    const int lane = tid & 31;
    const int wid  = tid >> 5;
    const int g    = lane >> 2;
    const int tg   = lane & 3;
    const int row0 = blockIdx.x * 128;

    float acc[16][4];
#pragma unroll
    for (int i = 0; i < 16; i++)
#pragma unroll
        for (int j = 0; j < 4; j++) acc[i][j] = 0.f;

    const int ar   = tid >> 1;
    const int ac0  = (tid & 1) * 32;
    const bool aok = (row0 + ar) < M;
    const float*    Ap    = A + (size_t)(row0 + ar) * F_IN + ac0;
    const uint32_t* Wp    = Wt + (size_t)ar * F_IN + ac0;
    uint32_t*       Asrow = As + ar * G1_STRIDE + ac0;
    uint32_t*       Bsrow = Bs + ar * G1_STRIDE + ac0;

    for (int c8 = 0; c8 < 8; c8++) {
        const int k0 = c8 * 64;
        __syncthreads();
#pragma unroll
        for (int q = 0; q < 8; q++) {
            float4 u = make_float4(0.f, 0.f, 0.f, 0.f);
            if (aok) u = *(const float4*)(Ap + k0 + q * 4);
            uint4 t4;
            t4.x = f2tf32(u.x); t4.y = f2tf32(u.y);
            t4.z = f2tf32(u.z); t4.w = f2tf32(u.w);
            *(uint4*)(Asrow + q * 4) = t4;
        }
#pragma unroll
        for (int q = 0; q < 8; q++)
            *(uint4*)(Bsrow + q * 4) = *(const uint4*)(Wp + k0 + q * 4);
        __syncthreads();

        const uint32_t* ap0 = As + (wid * 16 + g) * G1_STRIDE;
        const uint32_t* ap1 = ap0 + 8 * G1_STRIDE;
#pragma unroll
        for (int ks = 0; ks < 8; ks++) {
            const int k = ks * 8;
            uint32_t a0 = ap0[k + tg];
            uint32_t a1 = ap1[k + tg];
            uint32_t a2 = ap0[k + tg + 4];
            uint32_t a3 = ap1[k + tg + 4];
#pragma unroll
            for (int nt = 0; nt < 16; nt++) {
                const uint32_t* bp = Bs + (nt * 8 + g) * G1_STRIDE + k;
                uint32_t b0 = bp[tg];
                uint32_t b1 = bp[tg + 4];
                asm volatile(
                    "mma.sync.aligned.m16n8k8.row.col.f32.tf32.tf32.f32 "
                    "{%0,%1,%2,%3}, {%4,%5,%6,%7}, {%8,%9}, {%0,%1,%2,%3};"
                    : "+f"(acc[nt][0]), "+f"(acc[nt][1]),
                      "+f"(acc[nt][2]), "+f"(acc[nt][3])
                    : "r"(a0), "r"(a1), "r"(a2), "r"(a3), "r"(b0), "r"(b1));
            }
        }
    }

    const int r0 = row0 + wid * 16 + g;
    const int r1 = r0 + 8;
#pragma unroll
    for (int nt = 0; nt < 16; nt++) {
        const int col = nt * 8 + 2 * tg;
        if (r0 < M)
            *(__half2*)&S[(size_t)r0 * F_HID + col] =
                __floats2half2_rn(acc[nt][0], acc[nt][1]);
        if (r1 < M)
            *(__half2*)&S[(size_t)r1 * F_HID + col] =
                __floats2half2_rn(acc[nt][2], acc[nt][3]);
    }
}

// ---------------------------------------------------------------------------
// Fused: h = A @ support + b1 ; relu ; t = h @ W2.  Warp per row, fp16 gather,
// inner loop unrolled x4 (MLP=4).  Lane owns features [4*lane, 4*lane+4).
// ---------------------------------------------------------------------------
__global__ __launch_bounds__(256) void spmm1_gemm2_kernel(
    const int* __restrict__ rowptr, const int* __restrict__ ecol_s,
    const float* __restrict__ eval_s, const __half* __restrict__ S,
    const float* __restrict__ b1, const float* __restrict__ W2,
    float* __restrict__ T, int M) {
    __shared__ float Ws[F_HID * F_OUT];
    const int tid = threadIdx.x;
    for (int i = tid; i < F_HID * F_OUT; i += 256) Ws[i] = W2[i];
    __syncthreads();

    const int lane = tid & 31;
    const int wid  = tid >> 5;
    const int row  = blockIdx.x * 8 + wid;
    if (row >= M) return;

    float4 hb = *(const float4*)(b1 + lane * 4);
    float h0 = hb.x, h1 = hb.y, h2 = hb.z, h3 = hb.w;

    const int start = rowptr[row];
    const int end   = rowptr[row + 1];
    for (int base = start; base < end; base += 32) {
        int idx = base + lane;
        int   c = 0;
        float v = 0.f;
        if (idx < end) { c = ecol_s[idx]; v = eval_s[idx]; }
        int cnt = min(32, end - base);
        for (int j = 0; j < cnt; j += 4) {
            int   cc0 = __shfl_sync(0xffffffffu, c, j);
            int   cc1 = __shfl_sync(0xffffffffu, c, j + 1);
            int   cc2 = __shfl_sync(0xffffffffu, c, j + 2);
            int   cc3 = __shfl_sync(0xffffffffu, c, j + 3);
            float vv0 = __shfl_sync(0xffffffffu, v, j);
            float vv1 = __shfl_sync(0xffffffffu, v, j + 1);
            float vv2 = __shfl_sync(0xffffffffu, v, j + 2);
            float vv3 = __shfl_sync(0xffffffffu, v, j + 3);
            uint2 u0 = *(const uint2*)(S + (size_t)cc0 * F_HID + lane * 4);
            uint2 u1 = *(const uint2*)(S + (size_t)cc1 * F_HID + lane * 4);
            uint2 u2 = *(const uint2*)(S + (size_t)cc2 * F_HID + lane * 4);
            uint2 u3 = *(const uint2*)(S + (size_t)cc3 * F_HID + lane * 4);
#define ACC4(u, vv)                                                   \
            {                                                         \
                float2 fa = __half22float2(*(__half2*)&(u).x);        \
                float2 fb = __half22float2(*(__half2*)&(u).y);        \
                h0 = fmaf(fa.x, (vv), h0);                            \
                h1 = fmaf(fa.y, (vv), h1);                            \
                h2 = fmaf(fb.x, (vv), h2);                            \
                h3 = fmaf(fb.y, (vv), h3);                            \
            }
            ACC4(u0, vv0) ACC4(u1, vv1) ACC4(u2, vv2) ACC4(u3, vv3)
#undef ACC4
        }
    }
    h0 = fmaxf(h0, 0.f); h1 = fmaxf(h1, 0.f);
    h2 = fmaxf(h2, 0.f); h3 = fmaxf(h3, 0.f);

    float tacc = 0.f;
#pragma unroll 8
    for (int l = 0; l < 32; l++) {
        float a0 = __shfl_sync(0xffffffffu, h0, l);
        float a1 = __shfl_sync(0xffffffffu, h1, l);
        float a2 = __shfl_sync(0xffffffffu, h2, l);
        float a3 = __shfl_sync(0xffffffffu, h3, l);
        int k = l * 4;
        tacc = fmaf(a0, Ws[(k + 0) * F_OUT + lane], tacc);
        tacc = fmaf(a1, Ws[(k + 1) * F_OUT + lane], tacc);
        tacc = fmaf(a2, Ws[(k + 2) * F_OUT + lane], tacc);
        tacc = fmaf(a3, Ws[(k + 3) * F_OUT + lane], tacc);
    }
    T[(size_t)row * F_OUT + lane] = tacc;
}

// ---------------------------------------------------------------------------
// Fused: logits = A @ t + b2 ; log_softmax.  Warp per row, unrolled x4.
// ---------------------------------------------------------------------------
__global__ __launch_bounds__(256) void spmm2_lsm_kernel(
    const int* __restrict__ rowptr, const int* __restrict__ ecol_s,
    const float* __restrict__ eval_s, const float* __restrict__ T,
    const float* __restrict__ b2, float* __restrict__ out, int M) {
    const int tid  = threadIdx.x;
    const int lane = tid & 31;
    const int wid  = tid >> 5;
    const int row  = blockIdx.x * 8 + wid;
    if (row >= M) return;

    float acc = b2[lane];
    const int start = rowptr[row];
    const int end   = rowptr[row + 1];
    for (int base = start; base < end; base += 32) {
        int idx = base + lane;
        int   c = 0;
        float v = 0.f;
        if (idx < end) { c = ecol_s[idx]; v = eval_s[idx]; }
        int cnt = min(32, end - base);
        for (int j = 0; j < cnt; j += 4) {
            int   cc0 = __shfl_sync(0xffffffffu, c, j);
            int   cc1 = __shfl_sync(0xffffffffu, c, j + 1);
            int   cc2 = __shfl_sync(0xffffffffu, c, j + 2);
            int   cc3 = __shfl_sync(0xffffffffu, c, j + 3);
            float vv0 = __shfl_sync(0xffffffffu, v, j);
            float vv1 = __shfl_sync(0xffffffffu, v, j + 1);
            float vv2 = __shfl_sync(0xffffffffu, v, j + 2);
            float vv3 = __shfl_sync(0xffffffffu, v, j + 3);
            float t0 = __ldg(T + (size_t)cc0 * F_OUT + lane);
            float t1 = __ldg(T + (size_t)cc1 * F_OUT + lane);
            float t2 = __ldg(T + (size_t)cc2 * F_OUT + lane);
            float t3 = __ldg(T + (size_t)cc3 * F_OUT + lane);
            acc = fmaf(t0, vv0, acc);
            acc = fmaf(t1, vv1, acc);
            acc = fmaf(t2, vv2, acc);
            acc = fmaf(t3, vv3, acc);
        }
    }
    float m = acc;
#pragma unroll
    for (int o = 16; o; o >>= 1) m = fmaxf(m, __shfl_xor_sync(0xffffffffu, m, o));
    float ex = expf(acc - m);
    float s = ex;
#pragma unroll
    for (int o = 16; o; o >>= 1) s += __shfl_xor_sync(0xffffffffu, s, o);
    out[(size_t)row * F_OUT + lane] = acc - m - logf(s);
}

// ---------------------------------------------------------------------------
extern "C" void kernel_launch(void* const* d_in, const int* in_sizes, int n_in,
                              void* d_out, int out_size) {
    const float* x    = (const float*)d_in[0];
    const int*   erow = (const int*)d_in[1];
    const int*   ecol = (const int*)d_in[2];
    const float* ev   = (const float*)d_in[3];
    const float* W1   = (const float*)d_in[4];
    const float* b1   = (const float*)d_in[5];
    const float* W2   = (const float*)d_in[6];
    const float* b2   = (const float*)d_in[7];
    float* out = (float*)d_out;

    const int M = in_sizes[0] / F_IN;   // 100000
    const int E = in_sizes[1];          // 3200000

    __half* support;
    float *t, *evs;
    uint32_t* w1t;
    int *rowptr, *deg, *cursor, *ecs, *bsum;
    cudaGetSymbolAddress((void**)&support, g_support);
    cudaGetSymbolAddress((void**)&t,       g_t);
    cudaGetSymbolAddress((void**)&w1t,     g_w1t);
    cudaGetSymbolAddress((void**)&rowptr,  g_rowptr);
    cudaGetSymbolAddress((void**)&deg,     g_deg);
    cudaGetSymbolAddress((void**)&cursor,  g_cursor);
    cudaGetSymbolAddress((void**)&bsum,    g_bsum);
    cudaGetSymbolAddress((void**)&ecs,     g_ecol);
    cudaGetSymbolAddress((void**)&evs,     g_eval);

    const int nblk = (M + 1023) / 1024;

    // --- CSR build (deg zero via memset node; 5 kernel launches) ---
    cudaMemsetAsync(deg, 0, (size_t)M * sizeof(int));
    hist_kernel<<<(E + 255) / 256, 256>>>(erow, deg, E);
    scanA_kernel<<<nblk, 1024>>>(deg, rowptr, bsum, M);
    scanB_kernel<<<1, 256>>>(bsum, nblk);
    scanC_kernel<<<(M + 255) / 256, 256>>>(deg, rowptr, bsum, cursor, W1, w1t, M);
    scatter_kernel<<<(E + 255) / 256, 256>>>(erow, ecol, ev, cursor, ecs, evs, E);

    // --- support = x @ W1 (tf32 tensor cores) : 6th launch (ncu target) ---
    cudaFuncSetAttribute(gemm1_tf32_kernel,
                         cudaFuncAttributeMaxDynamicSharedMemorySize,
                         G1_SMEM_BYTES);
    gemm1_tf32_kernel<<<(M + 127) / 128, 256, G1_SMEM_BYTES>>>(x, w1t, support, M);

    // --- t = relu(A @ support + b1) @ W2 ---
    spmm1_gemm2_kernel<<<(M + 7) / 8, 256>>>(rowptr, ecs, evs, support, b1, W2,
                                             t, M);

    // --- out = log_softmax(A @ t + b2) ---
    spmm2_lsm_kernel<<<(M + 7) / 8, 256>>>(rowptr, ecs, evs, t, b2, out, M);
}

// round 6
// speedup vs baseline: 3.2732x; 1.0924x over previous
#include <cuda_runtime.h>
#include <cuda_fp16.h>
#include <math.h>
#include <stdint.h>

#define N_NODES_MAX 100000
#define E_MAX       3300000
#define F_IN  512
#define F_HID 128
#define F_OUT 32

// Scratch (allocation-free rule: __device__ globals)
__device__ __half   g_support[(size_t)N_NODES_MAX * F_HID];  // x @ W1 (fp16)
__device__ __half   g_t[(size_t)N_NODES_MAX * F_OUT];        // relu(h)@W2 (fp16)
__device__ uint32_t g_w1t[F_IN * F_HID];  // W1^T as tf32 bits, [n][k]
__device__ int      g_rowptr[N_NODES_MAX + 1];
__device__ int      g_deg[N_NODES_MAX];
__device__ int      g_cursor[N_NODES_MAX];
__device__ int      g_bsum[256];
__device__ int2     g_edge[E_MAX];        // packed (col, val bits), row-sorted

__device__ __forceinline__ uint32_t f2tf32(float f) {
    uint32_t r;
    asm("cvt.rna.tf32.f32 %0, %1;" : "=r"(r) : "f"(f));
    return r;
}
__device__ __forceinline__ uint32_t smem_u32(const void* p) {
    uint32_t a;
    asm("{ .reg .u64 t; cvta.to.shared.u64 t, %1; cvt.u32.u64 %0, t; }"
        : "=r"(a) : "l"(p));
    return a;
}
__device__ __forceinline__ void cp16(uint32_t dst, const void* src, int srcsz) {
    asm volatile("cp.async.cg.shared.global [%0], [%1], 16, %2;"
                 :: "r"(dst), "l"(src), "r"(srcsz));
}
__device__ __forceinline__ void cp_commit() {
    asm volatile("cp.async.commit_group;" ::: "memory");
}
template <int N>
__device__ __forceinline__ void cp_wait() {
    asm volatile("cp.async.wait_group %0;" :: "n"(N) : "memory");
}

// ---------------------------------------------------------------------------
// CSR build
// ---------------------------------------------------------------------------
__global__ void hist_kernel(const int* __restrict__ erow, int* __restrict__ deg,
                            int E) {
    int e = blockIdx.x * blockDim.x + threadIdx.x;
    if (e < E) atomicAdd(&deg[erow[e]], 1);
}

__global__ __launch_bounds__(1024) void scanA_kernel(const int* __restrict__ deg,
                                                     int* __restrict__ rowptr,
                                                     int* __restrict__ bsum,
                                                     int n) {
    __shared__ int wsum[32];
    const int tid  = threadIdx.x;
    const int lane = tid & 31;
    const int wid  = tid >> 5;
    int i = blockIdx.x * 1024 + tid;
    int v = (i < n) ? deg[i] : 0;
    int x = v;
#pragma unroll
    for (int o = 1; o < 32; o <<= 1) {
        int t = __shfl_up_sync(0xffffffffu, x, o);
        if (lane >= o) x += t;
    }
    if (lane == 31) wsum[wid] = x;
    __syncthreads();
    if (wid == 0) {
        int w = wsum[lane];
#pragma unroll
        for (int o = 1; o < 32; o <<= 1) {
            int t = __shfl_up_sync(0xffffffffu, w, o);
            if (lane >= o) w += t;
        }
        wsum[lane] = w;
    }
    __syncthreads();
    int inc = x + (wid > 0 ? wsum[wid - 1] : 0);
    if (i < n) rowptr[i + 1] = inc;
    if (tid == 1023) bsum[blockIdx.x] = inc;
}

__global__ __launch_bounds__(256) void scanB_kernel(int* __restrict__ bsum,
                                                    int nblk) {
    __shared__ int wsum[8];
    const int tid  = threadIdx.x;
    const int lane = tid & 31;
    const int wid  = tid >> 5;
    int v = (tid < nblk) ? bsum[tid] : 0;
    int x = v;
#pragma unroll
    for (int o = 1; o < 32; o <<= 1) {
        int t = __shfl_up_sync(0xffffffffu, x, o);
        if (lane >= o) x += t;
    }
    if (lane == 31) wsum[wid] = x;
    __syncthreads();
    if (wid == 0 && lane < 8) {
        int w = wsum[lane];
#pragma unroll
        for (int o = 1; o < 8; o <<= 1) {
            int t = __shfl_up_sync(0xffu, w, o);
            if (lane >= o) w += t;
        }
        wsum[lane] = w;
    }
    __syncthreads();
    int inc = x + (wid > 0 ? wsum[wid - 1] : 0);
    if (tid < nblk) bsum[tid] = inc - v;
}

// Phase C: finalize rowptr/cursor; also convert+transpose W1 -> tf32 bits.
__global__ void scanC_kernel(const int* __restrict__ deg,
                             int* __restrict__ rowptr,
                             const int* __restrict__ bsum,
                             int* __restrict__ cursor,
                             const float* __restrict__ W1,
                             uint32_t* __restrict__ w1t, int n) {
    int i = blockIdx.x * blockDim.x + threadIdx.x;
    if (i < F_IN * F_HID) {
        int k  = i >> 7;
        int nn = i & 127;
        w1t[nn * F_IN + k] = f2tf32(W1[i]);
    }
    if (i >= n) return;
    int inc = rowptr[i + 1] + bsum[i >> 10];
    rowptr[i + 1] = inc;
    cursor[i] = inc - deg[i];
    if (i == 0) rowptr[0] = 0;
}

__global__ void scatter_kernel(const int* __restrict__ erow,
                               const int* __restrict__ ecol,
                               const float* __restrict__ ev,
                               int* __restrict__ cursor,
                               int2* __restrict__ edge, int E) {
    int e = blockIdx.x * blockDim.x + threadIdx.x;
    if (e >= E) return;
    int r = erow[e];
    int pos = atomicAdd(&cursor[r], 1);
    edge[pos] = make_int2(ecol[e], __float_as_int(ev[e]));
}

// ---------------------------------------------------------------------------
// GEMM1: S[M,128] = tf32(A[M,512]) @ tf32(W1) -> fp16 out.
// cp.async 2-stage pipeline; A fed as raw fp32 bits (HW tf32 truncation).
// 128x128 CTA tile, 256 threads, k chunk = 64, stride 68 words.
// ---------------------------------------------------------------------------
#define G1_STRIDE 68
#define G1_STAGE_WORDS (2 * 128 * G1_STRIDE)                 // A + B per stage
#define G1_SMEM_BYTES  (2 * G1_STAGE_WORDS * 4)              // 2 stages

extern __shared__ uint32_t g1smem[];

__global__ __launch_bounds__(256, 1) void gemm1_tf32_kernel(
    const float* __restrict__ A, const uint32_t* __restrict__ Wt,
    __half* __restrict__ S, int M) {
    const int tid  = threadIdx.x;
    const int lane = tid & 31;
    const int wid  = tid >> 5;
    const int g    = lane >> 2;
    const int tg   = lane & 3;
    const int row0 = blockIdx.x * 128;

    float acc[16][4];
#pragma unroll
    for (int i = 0; i < 16; i++)
#pragma unroll
        for (int j = 0; j < 4; j++) acc[i][j] = 0.f;

    const int ar   = tid >> 1;
    const int ac0  = (tid & 1) * 32;
    const bool aok = (row0 + ar) < M;
    const int asz  = aok ? 16 : 0;
    const float*    Ag = A + (size_t)(row0 + ar) * F_IN + ac0;
    const uint32_t* Bg = Wt + (size_t)ar * F_IN + ac0;

    const uint32_t sbase = smem_u32(g1smem);
    uint32_t dA[2], dB[2];
#pragma unroll
    for (int s = 0; s < 2; s++) {
        dA[s] = sbase + (uint32_t)(s * G1_STAGE_WORDS + ar * G1_STRIDE + ac0) * 4;
        dB[s] = dA[s] + (uint32_t)(128 * G1_STRIDE) * 4;
    }

#define G1_ISSUE(cc, st)                                                  \
    {                                                                     \
        const int kk = (cc) * 64;                                         \
        _Pragma("unroll")                                                 \
        for (int q = 0; q < 8; q++)                                       \
            cp16(dA[st] + q * 16, Ag + kk + q * 4, asz);                  \
        _Pragma("unroll")                                                 \
        for (int q = 0; q < 8; q++)                                       \
            cp16(dB[st] + q * 16, Bg + kk + q * 4, 16);                   \
    }

    G1_ISSUE(0, 0);
    cp_commit();

    for (int c = 0; c < 8; c++) {
        if (c < 7) {
            G1_ISSUE(c + 1, (c + 1) & 1);
            cp_commit();
            cp_wait<1>();
        } else {
            cp_wait<0>();
        }
        __syncthreads();

        const uint32_t* As = g1smem + (c & 1) * G1_STAGE_WORDS;
        const uint32_t* Bs = As + 128 * G1_STRIDE;
        const uint32_t* ap0 = As + (wid * 16 + g) * G1_STRIDE;
        const uint32_t* ap1 = ap0 + 8 * G1_STRIDE;
#pragma unroll
        for (int ks = 0; ks < 8; ks++) {
            const int k = ks * 8;
            uint32_t a0 = ap0[k + tg];
            uint32_t a1 = ap1[k + tg];
            uint32_t a2 = ap0[k + tg + 4];
            uint32_t a3 = ap1[k + tg + 4];
#pragma unroll
            for (int nt = 0; nt < 16; nt++) {
                const uint32_t* bp = Bs + (nt * 8 + g) * G1_STRIDE + k;
                uint32_t b0 = bp[tg];
                uint32_t b1 = bp[tg + 4];
                asm volatile(
                    "mma.sync.aligned.m16n8k8.row.col.f32.tf32.tf32.f32 "
                    "{%0,%1,%2,%3}, {%4,%5,%6,%7}, {%8,%9}, {%0,%1,%2,%3};"
                    : "+f"(acc[nt][0]), "+f"(acc[nt][1]),
                      "+f"(acc[nt][2]), "+f"(acc[nt][3])
                    : "r"(a0), "r"(a1), "r"(a2), "r"(a3), "r"(b0), "r"(b1));
            }
        }
        __syncthreads();
    }
#undef G1_ISSUE

    const int r0 = row0 + wid * 16 + g;
    const int r1 = r0 + 8;
#pragma unroll
    for (int nt = 0; nt < 16; nt++) {
        const int col = nt * 8 + 2 * tg;
        if (r0 < M)
            *(__half2*)&S[(size_t)r0 * F_HID + col] =
                __floats2half2_rn(acc[nt][0], acc[nt][1]);
        if (r1 < M)
            *(__half2*)&S[(size_t)r1 * F_HID + col] =
                __floats2half2_rn(acc[nt][2], acc[nt][3]);
    }
}

// ---------------------------------------------------------------------------
// Fused: h = A @ support + b1 ; relu ; t = h @ W2 (fp16 out).
// Warp per row, fp16 gather, inner loop unrolled x4.
// ---------------------------------------------------------------------------
__global__ __launch_bounds__(256) void spmm1_gemm2_kernel(
    const int* __restrict__ rowptr, const int2* __restrict__ edge,
    const __half* __restrict__ S, const float* __restrict__ b1,
    const float* __restrict__ W2, __half* __restrict__ T, int M) {
    __shared__ float Ws[F_HID * F_OUT];
    const int tid = threadIdx.x;
    for (int i = tid; i < F_HID * F_OUT; i += 256) Ws[i] = W2[i];
    __syncthreads();

    const int lane = tid & 31;
    const int wid  = tid >> 5;
    const int row  = blockIdx.x * 8 + wid;
    if (row >= M) return;

    float4 hb = *(const float4*)(b1 + lane * 4);
    float h0 = hb.x, h1 = hb.y, h2 = hb.z, h3 = hb.w;

    const int start = rowptr[row];
    const int end   = rowptr[row + 1];
    for (int base = start; base < end; base += 32) {
        int idx = base + lane;
        int2 e = make_int2(0, 0);
        if (idx < end) e = edge[idx];
        int cnt = min(32, end - base);
        for (int j = 0; j < cnt; j += 4) {
            int   cc0 = __shfl_sync(0xffffffffu, e.x, j);
            int   cc1 = __shfl_sync(0xffffffffu, e.x, j + 1);
            int   cc2 = __shfl_sync(0xffffffffu, e.x, j + 2);
            int   cc3 = __shfl_sync(0xffffffffu, e.x, j + 3);
            float vv0 = __int_as_float(__shfl_sync(0xffffffffu, e.y, j));
            float vv1 = __int_as_float(__shfl_sync(0xffffffffu, e.y, j + 1));
            float vv2 = __int_as_float(__shfl_sync(0xffffffffu, e.y, j + 2));
            float vv3 = __int_as_float(__shfl_sync(0xffffffffu, e.y, j + 3));
            uint2 u0 = *(const uint2*)(S + (size_t)cc0 * F_HID + lane * 4);
            uint2 u1 = *(const uint2*)(S + (size_t)cc1 * F_HID + lane * 4);
            uint2 u2 = *(const uint2*)(S + (size_t)cc2 * F_HID + lane * 4);
            uint2 u3 = *(const uint2*)(S + (size_t)cc3 * F_HID + lane * 4);
#define ACC4(u, vv)                                                   \
            {                                                         \
                float2 fa = __half22float2(*(__half2*)&(u).x);        \
                float2 fb = __half22float2(*(__half2*)&(u).y);        \
                h0 = fmaf(fa.x, (vv), h0);                            \
                h1 = fmaf(fa.y, (vv), h1);                            \
                h2 = fmaf(fb.x, (vv), h2);                            \
                h3 = fmaf(fb.y, (vv), h3);                            \
            }
            ACC4(u0, vv0) ACC4(u1, vv1) ACC4(u2, vv2) ACC4(u3, vv3)
#undef ACC4
        }
    }
    h0 = fmaxf(h0, 0.f); h1 = fmaxf(h1, 0.f);
    h2 = fmaxf(h2, 0.f); h3 = fmaxf(h3, 0.f);

    float tacc = 0.f;
#pragma unroll 8
    for (int l = 0; l < 32; l++) {
        float a0 = __shfl_sync(0xffffffffu, h0, l);
        float a1 = __shfl_sync(0xffffffffu, h1, l);
        float a2 = __shfl_sync(0xffffffffu, h2, l);
        float a3 = __shfl_sync(0xffffffffu, h3, l);
        int k = l * 4;
        tacc = fmaf(a0, Ws[(k + 0) * F_OUT + lane], tacc);
        tacc = fmaf(a1, Ws[(k + 1) * F_OUT + lane], tacc);
        tacc = fmaf(a2, Ws[(k + 2) * F_OUT + lane], tacc);
        tacc = fmaf(a3, Ws[(k + 3) * F_OUT + lane], tacc);
    }
    T[(size_t)row * F_OUT + lane] = __float2half_rn(tacc);
}

// ---------------------------------------------------------------------------
// Fused: logits = A @ t + b2 ; log_softmax.  Warp per row, fp16 gather.
// ---------------------------------------------------------------------------
__global__ __launch_bounds__(256) void spmm2_lsm_kernel(
    const int* __restrict__ rowptr, const int2* __restrict__ edge,
    const __half* __restrict__ T, const float* __restrict__ b2,
    float* __restrict__ out, int M) {
    const int tid  = threadIdx.x;
    const int lane = tid & 31;
    const int wid  = tid >> 5;
    const int row  = blockIdx.x * 8 + wid;
    if (row >= M) return;

    float acc = b2[lane];
    const int start = rowptr[row];
    const int end   = rowptr[row + 1];
    for (int base = start; base < end; base += 32) {
        int idx = base + lane;
        int2 e = make_int2(0, 0);
        if (idx < end) e = edge[idx];
        int cnt = min(32, end - base);
        for (int j = 0; j < cnt; j += 4) {
            int   cc0 = __shfl_sync(0xffffffffu, e.x, j);
            int   cc1 = __shfl_sync(0xffffffffu, e.x, j + 1);
            int   cc2 = __shfl_sync(0xffffffffu, e.x, j + 2);
            int   cc3 = __shfl_sync(0xffffffffu, e.x, j + 3);
            float vv0 = __int_as_float(__shfl_sync(0xffffffffu, e.y, j));
            float vv1 = __int_as_float(__shfl_sync(0xffffffffu, e.y, j + 1));
            float vv2 = __int_as_float(__shfl_sync(0xffffffffu, e.y, j + 2));
            float vv3 = __int_as_float(__shfl_sync(0xffffffffu, e.y, j + 3));
            float t0 = __half2float(T[(size_t)cc0 * F_OUT + lane]);
            float t1 = __half2float(T[(size_t)cc1 * F_OUT + lane]);
            float t2 = __half2float(T[(size_t)cc2 * F_OUT + lane]);
            float t3 = __half2float(T[(size_t)cc3 * F_OUT + lane]);
            acc = fmaf(t0, vv0, acc);
            acc = fmaf(t1, vv1, acc);
            acc = fmaf(t2, vv2, acc);
            acc = fmaf(t3, vv3, acc);
        }
    }
    float m = acc;
#pragma unroll
    for (int o = 16; o; o >>= 1) m = fmaxf(m, __shfl_xor_sync(0xffffffffu, m, o));
    float ex = expf(acc - m);
    float s = ex;
#pragma unroll
    for (int o = 16; o; o >>= 1) s += __shfl_xor_sync(0xffffffffu, s, o);
    out[(size_t)row * F_OUT + lane] = acc - m - logf(s);
}

// ---------------------------------------------------------------------------
extern "C" void kernel_launch(void* const* d_in, const int* in_sizes, int n_in,
                              void* d_out, int out_size) {
    const float* x    = (const float*)d_in[0];
    const int*   erow = (const int*)d_in[1];
    const int*   ecol = (const int*)d_in[2];
    const float* ev   = (const float*)d_in[3];
    const float* W1   = (const float*)d_in[4];
    const float* b1   = (const float*)d_in[5];
    const float* W2   = (const float*)d_in[6];
    const float* b2   = (const float*)d_in[7];
    float* out = (float*)d_out;

    const int M = in_sizes[0] / F_IN;   // 100000
    const int E = in_sizes[1];          // 3200000

    __half *support, *t;
    uint32_t* w1t;
    int2* edge;
    int *rowptr, *deg, *cursor, *bsum;
    cudaGetSymbolAddress((void**)&support, g_support);
    cudaGetSymbolAddress((void**)&t,       g_t);
    cudaGetSymbolAddress((void**)&w1t,     g_w1t);
    cudaGetSymbolAddress((void**)&rowptr,  g_rowptr);
    cudaGetSymbolAddress((void**)&deg,     g_deg);
    cudaGetSymbolAddress((void**)&cursor,  g_cursor);
    cudaGetSymbolAddress((void**)&bsum,    g_bsum);
    cudaGetSymbolAddress((void**)&edge,    g_edge);

    const int nblk = (M + 1023) / 1024;

    // --- CSR build ---
    cudaMemsetAsync(deg, 0, (size_t)M * sizeof(int));
    hist_kernel<<<(E + 255) / 256, 256>>>(erow, deg, E);
    scanA_kernel<<<nblk, 1024>>>(deg, rowptr, bsum, M);
    scanB_kernel<<<1, 256>>>(bsum, nblk);
    scanC_kernel<<<(M + 255) / 256, 256>>>(deg, rowptr, bsum, cursor, W1, w1t, M);
    scatter_kernel<<<(E + 255) / 256, 256>>>(erow, ecol, ev, cursor, edge, E);

    // --- support = x @ W1 (tf32 tensor cores, cp.async pipeline) ---
    cudaFuncSetAttribute(gemm1_tf32_kernel,
                         cudaFuncAttributeMaxDynamicSharedMemorySize,
                         G1_SMEM_BYTES);
    gemm1_tf32_kernel<<<(M + 127) / 128, 256, G1_SMEM_BYTES>>>(x, w1t, support, M);

    // --- t = relu(A @ support + b1) @ W2  (fp16 out) ---
    spmm1_gemm2_kernel<<<(M + 7) / 8, 256>>>(rowptr, edge, support, b1, W2, t, M);

    // --- out = log_softmax(A @ t + b2) ---
    spmm2_lsm_kernel<<<(M + 7) / 8, 256>>>(rowptr, edge, t, b2, out, M);
}

// round 7
// speedup vs baseline: 3.4413x; 1.0513x over previous
#include <cuda_runtime.h>
#include <cuda_fp16.h>
#include <math.h>
#include <stdint.h>

#define N_NODES_MAX 100000
#define E_MAX       3300000
#define F_IN  512
#define F_HID 128
#define F_OUT 32

// Scratch (allocation-free rule: __device__ globals)
__device__ __half   g_support[(size_t)N_NODES_MAX * F_HID];  // x @ W1 (fp16)
__device__ __half   g_t[(size_t)N_NODES_MAX * F_OUT];        // relu(h)@W2 (fp16)
__device__ uint32_t g_w1t[F_IN * F_HID];  // W1^T as tf32 bits, [n][k]
__device__ int      g_rowptr[N_NODES_MAX + 1];
__device__ int      g_deg[N_NODES_MAX];
__device__ int      g_cursor[N_NODES_MAX];
__device__ int      g_bsum[256];
__device__ int2     g_edge[E_MAX];        // packed (col, val bits), row-sorted

__device__ __forceinline__ uint32_t f2tf32(float f) {
    uint32_t r;
    asm("cvt.rna.tf32.f32 %0, %1;" : "=r"(r) : "f"(f));
    return r;
}
__device__ __forceinline__ uint32_t smem_u32(const void* p) {
    uint32_t a;
    asm("{ .reg .u64 t; cvta.to.shared.u64 t, %1; cvt.u32.u64 %0, t; }"
        : "=r"(a) : "l"(p));
    return a;
}
__device__ __forceinline__ void cp16(uint32_t dst, const void* src, int srcsz) {
    asm volatile("cp.async.cg.shared.global [%0], [%1], 16, %2;"
                 :: "r"(dst), "l"(src), "r"(srcsz));
}
__device__ __forceinline__ void cp_commit() {
    asm volatile("cp.async.commit_group;" ::: "memory");
}
template <int N>
__device__ __forceinline__ void cp_wait() {
    asm volatile("cp.async.wait_group %0;" :: "n"(N) : "memory");
}

// ---------------------------------------------------------------------------
// W1 convert+transpose -> tf32 bits  (runs on GEMM branch stream)
// ---------------------------------------------------------------------------
__global__ void w1conv_kernel(const float* __restrict__ W1,
                              uint32_t* __restrict__ w1t) {
    int i = blockIdx.x * blockDim.x + threadIdx.x;
    if (i < F_IN * F_HID) {
        int k  = i >> 7;
        int nn = i & 127;
        w1t[nn * F_IN + k] = f2tf32(W1[i]);
    }
}

// ---------------------------------------------------------------------------
// CSR build
// ---------------------------------------------------------------------------
__global__ void hist_kernel(const int* __restrict__ erow, int* __restrict__ deg,
                            int E) {
    int e = blockIdx.x * blockDim.x + threadIdx.x;
    if (e < E) atomicAdd(&deg[erow[e]], 1);
}

__global__ __launch_bounds__(1024) void scanA_kernel(const int* __restrict__ deg,
                                                     int* __restrict__ rowptr,
                                                     int* __restrict__ bsum,
                                                     int n) {
    __shared__ int wsum[32];
    const int tid  = threadIdx.x;
    const int lane = tid & 31;
    const int wid  = tid >> 5;
    int i = blockIdx.x * 1024 + tid;
    int v = (i < n) ? deg[i] : 0;
    int x = v;
#pragma unroll
    for (int o = 1; o < 32; o <<= 1) {
        int t = __shfl_up_sync(0xffffffffu, x, o);
        if (lane >= o) x += t;
    }
    if (lane == 31) wsum[wid] = x;
    __syncthreads();
    if (wid == 0) {
        int w = wsum[lane];
#pragma unroll
        for (int o = 1; o < 32; o <<= 1) {
            int t = __shfl_up_sync(0xffffffffu, w, o);
            if (lane >= o) w += t;
        }
        wsum[lane] = w;
    }
    __syncthreads();
    int inc = x + (wid > 0 ? wsum[wid - 1] : 0);
    if (i < n) rowptr[i + 1] = inc;
    if (tid == 1023) bsum[blockIdx.x] = inc;
}

__global__ __launch_bounds__(256) void scanB_kernel(int* __restrict__ bsum,
                                                    int nblk) {
    __shared__ int wsum[8];
    const int tid  = threadIdx.x;
    const int lane = tid & 31;
    const int wid  = tid >> 5;
    int v = (tid < nblk) ? bsum[tid] : 0;
    int x = v;
#pragma unroll
    for (int o = 1; o < 32; o <<= 1) {
        int t = __shfl_up_sync(0xffffffffu, x, o);
        if (lane >= o) x += t;
    }
    if (lane == 31) wsum[wid] = x;
    __syncthreads();
    if (wid == 0 && lane < 8) {
        int w = wsum[lane];
#pragma unroll
        for (int o = 1; o < 8; o <<= 1) {
            int t = __shfl_up_sync(0xffu, w, o);
            if (lane >= o) w += t;
        }
        wsum[lane] = w;
    }
    __syncthreads();
    int inc = x + (wid > 0 ? wsum[wid - 1] : 0);
    if (tid < nblk) bsum[tid] = inc - v;
}

__global__ void scanC_kernel(const int* __restrict__ deg,
                             int* __restrict__ rowptr,
                             const int* __restrict__ bsum,
                             int* __restrict__ cursor, int n) {
    int i = blockIdx.x * blockDim.x + threadIdx.x;
    if (i >= n) return;
    int inc = rowptr[i + 1] + bsum[i >> 10];
    rowptr[i + 1] = inc;
    cursor[i] = inc - deg[i];
    if (i == 0) rowptr[0] = 0;
}

__global__ void scatter_kernel(const int* __restrict__ erow,
                               const int* __restrict__ ecol,
                               const float* __restrict__ ev,
                               int* __restrict__ cursor,
                               int2* __restrict__ edge, int E) {
    int e = blockIdx.x * blockDim.x + threadIdx.x;
    if (e >= E) return;
    int r = erow[e];
    int pos = atomicAdd(&cursor[r], 1);
    edge[pos] = make_int2(ecol[e], __float_as_int(ev[e]));
}

// ---------------------------------------------------------------------------
// GEMM1: S[M,128] = tf32(A[M,512]) @ tf32(W1) -> fp16 out.
// cp.async 2-stage pipeline; A fed as raw fp32 bits (HW tf32 truncation).
// ---------------------------------------------------------------------------
#define G1_STRIDE 68
#define G1_STAGE_WORDS (2 * 128 * G1_STRIDE)
#define G1_SMEM_BYTES  (2 * G1_STAGE_WORDS * 4)

extern __shared__ uint32_t g1smem[];

__global__ __launch_bounds__(256, 1) void gemm1_tf32_kernel(
    const float* __restrict__ A, const uint32_t* __restrict__ Wt,
    __half* __restrict__ S, int M) {
    const int tid  = threadIdx.x;
    const int lane = tid & 31;
    const int wid  = tid >> 5;
    const int g    = lane >> 2;
    const int tg   = lane & 3;
    const int row0 = blockIdx.x * 128;

    float acc[16][4];
#pragma unroll
    for (int i = 0; i < 16; i++)
#pragma unroll
        for (int j = 0; j < 4; j++) acc[i][j] = 0.f;

    const int ar   = tid >> 1;
    const int ac0  = (tid & 1) * 32;
    const bool aok = (row0 + ar) < M;
    const int asz  = aok ? 16 : 0;
    const float*    Ag = A + (size_t)(row0 + ar) * F_IN + ac0;
    const uint32_t* Bg = Wt + (size_t)ar * F_IN + ac0;

    const uint32_t sbase = smem_u32(g1smem);
    uint32_t dA[2], dB[2];
#pragma unroll
    for (int s = 0; s < 2; s++) {
        dA[s] = sbase + (uint32_t)(s * G1_STAGE_WORDS + ar * G1_STRIDE + ac0) * 4;
        dB[s] = dA[s] + (uint32_t)(128 * G1_STRIDE) * 4;
    }

#define G1_ISSUE(cc, st)                                                  \
    {                                                                     \
        const int kk = (cc) * 64;                                         \
        _Pragma("unroll")                                                 \
        for (int q = 0; q < 8; q++)                                       \
            cp16(dA[st] + q * 16, Ag + kk + q * 4, asz);                  \
        _Pragma("unroll")                                                 \
        for (int q = 0; q < 8; q++)                                       \
            cp16(dB[st] + q * 16, Bg + kk + q * 4, 16);                   \
    }

    G1_ISSUE(0, 0);
    cp_commit();

    for (int c = 0; c < 8; c++) {
        if (c < 7) {
            G1_ISSUE(c + 1, (c + 1) & 1);
            cp_commit();
            cp_wait<1>();
        } else {
            cp_wait<0>();
        }
        __syncthreads();

        const uint32_t* As = g1smem + (c & 1) * G1_STAGE_WORDS;
        const uint32_t* Bs = As + 128 * G1_STRIDE;
        const uint32_t* ap0 = As + (wid * 16 + g) * G1_STRIDE;
        const uint32_t* ap1 = ap0 + 8 * G1_STRIDE;
#pragma unroll
        for (int ks = 0; ks < 8; ks++) {
            const int k = ks * 8;
            uint32_t a0 = ap0[k + tg];
            uint32_t a1 = ap1[k + tg];
            uint32_t a2 = ap0[k + tg + 4];
            uint32_t a3 = ap1[k + tg + 4];
#pragma unroll
            for (int nt = 0; nt < 16; nt++) {
                const uint32_t* bp = Bs + (nt * 8 + g) * G1_STRIDE + k;
                uint32_t b0 = bp[tg];
                uint32_t b1 = bp[tg + 4];
                asm volatile(
                    "mma.sync.aligned.m16n8k8.row.col.f32.tf32.tf32.f32 "
                    "{%0,%1,%2,%3}, {%4,%5,%6,%7}, {%8,%9}, {%0,%1,%2,%3};"
                    : "+f"(acc[nt][0]), "+f"(acc[nt][1]),
                      "+f"(acc[nt][2]), "+f"(acc[nt][3])
                    : "r"(a0), "r"(a1), "r"(a2), "r"(a3), "r"(b0), "r"(b1));
            }
        }
        __syncthreads();
    }
#undef G1_ISSUE

    const int r0 = row0 + wid * 16 + g;
    const int r1 = r0 + 8;
#pragma unroll
    for (int nt = 0; nt < 16; nt++) {
        const int col = nt * 8 + 2 * tg;
        if (r0 < M)
            *(__half2*)&S[(size_t)r0 * F_HID + col] =
                __floats2half2_rn(acc[nt][0], acc[nt][1]);
        if (r1 < M)
            *(__half2*)&S[(size_t)r1 * F_HID + col] =
                __floats2half2_rn(acc[nt][2], acc[nt][3]);
    }
}

// ---------------------------------------------------------------------------
// Fused: h = A @ support + b1 ; relu ; t = h @ W2 (fp16 out).
// ---------------------------------------------------------------------------
__global__ __launch_bounds__(256) void spmm1_gemm2_kernel(
    const int* __restrict__ rowptr, const int2* __restrict__ edge,
    const __half* __restrict__ S, const float* __restrict__ b1,
    const float* __restrict__ W2, __half* __restrict__ T, int M) {
    __shared__ float Ws[F_HID * F_OUT];
    const int tid = threadIdx.x;
    for (int i = tid; i < F_HID * F_OUT; i += 256) Ws[i] = W2[i];
    __syncthreads();

    const int lane = tid & 31;
    const int wid  = tid >> 5;
    const int row  = blockIdx.x * 8 + wid;
    if (row >= M) return;

    float4 hb = *(const float4*)(b1 + lane * 4);
    float h0 = hb.x, h1 = hb.y, h2 = hb.z, h3 = hb.w;

    const int start = rowptr[row];
    const int end   = rowptr[row + 1];
    for (int base = start; base < end; base += 32) {
        int idx = base + lane;
        int2 e = make_int2(0, 0);
        if (idx < end) e = edge[idx];
        int cnt = min(32, end - base);
        for (int j = 0; j < cnt; j += 4) {
            int   cc0 = __shfl_sync(0xffffffffu, e.x, j);
            int   cc1 = __shfl_sync(0xffffffffu, e.x, j + 1);
            int   cc2 = __shfl_sync(0xffffffffu, e.x, j + 2);
            int   cc3 = __shfl_sync(0xffffffffu, e.x, j + 3);
            float vv0 = __int_as_float(__shfl_sync(0xffffffffu, e.y, j));
            float vv1 = __int_as_float(__shfl_sync(0xffffffffu, e.y, j + 1));
            float vv2 = __int_as_float(__shfl_sync(0xffffffffu, e.y, j + 2));
            float vv3 = __int_as_float(__shfl_sync(0xffffffffu, e.y, j + 3));
            uint2 u0 = *(const uint2*)(S + (size_t)cc0 * F_HID + lane * 4);
            uint2 u1 = *(const uint2*)(S + (size_t)cc1 * F_HID + lane * 4);
            uint2 u2 = *(const uint2*)(S + (size_t)cc2 * F_HID + lane * 4);
            uint2 u3 = *(const uint2*)(S + (size_t)cc3 * F_HID + lane * 4);
#define ACC4(u, vv)                                                   \
            {                                                         \
                float2 fa = __half22float2(*(__half2*)&(u).x);        \
                float2 fb = __half22float2(*(__half2*)&(u).y);        \
                h0 = fmaf(fa.x, (vv), h0);                            \
                h1 = fmaf(fa.y, (vv), h1);                            \
                h2 = fmaf(fb.x, (vv), h2);                            \
                h3 = fmaf(fb.y, (vv), h3);                            \
            }
            ACC4(u0, vv0) ACC4(u1, vv1) ACC4(u2, vv2) ACC4(u3, vv3)
#undef ACC4
        }
    }
    h0 = fmaxf(h0, 0.f); h1 = fmaxf(h1, 0.f);
    h2 = fmaxf(h2, 0.f); h3 = fmaxf(h3, 0.f);

    float tacc = 0.f;
#pragma unroll 8
    for (int l = 0; l < 32; l++) {
        float a0 = __shfl_sync(0xffffffffu, h0, l);
        float a1 = __shfl_sync(0xffffffffu, h1, l);
        float a2 = __shfl_sync(0xffffffffu, h2, l);
        float a3 = __shfl_sync(0xffffffffu, h3, l);
        int k = l * 4;
        tacc = fmaf(a0, Ws[(k + 0) * F_OUT + lane], tacc);
        tacc = fmaf(a1, Ws[(k + 1) * F_OUT + lane], tacc);
        tacc = fmaf(a2, Ws[(k + 2) * F_OUT + lane], tacc);
        tacc = fmaf(a3, Ws[(k + 3) * F_OUT + lane], tacc);
    }
    T[(size_t)row * F_OUT + lane] = __float2half_rn(tacc);
}

// ---------------------------------------------------------------------------
// Fused: logits = A @ t + b2 ; log_softmax.
// ---------------------------------------------------------------------------
__global__ __launch_bounds__(256) void spmm2_lsm_kernel(
    const int* __restrict__ rowptr, const int2* __restrict__ edge,
    const __half* __restrict__ T, const float* __restrict__ b2,
    float* __restrict__ out, int M) {
    const int tid  = threadIdx.x;
    const int lane = tid & 31;
    const int wid  = tid >> 5;
    const int row  = blockIdx.x * 8 + wid;
    if (row >= M) return;

    float acc = b2[lane];
    const int start = rowptr[row];
    const int end   = rowptr[row + 1];
    for (int base = start; base < end; base += 32) {
        int idx = base + lane;
        int2 e = make_int2(0, 0);
        if (idx < end) e = edge[idx];
        int cnt = min(32, end - base);
        for (int j = 0; j < cnt; j += 4) {
            int   cc0 = __shfl_sync(0xffffffffu, e.x, j);
            int   cc1 = __shfl_sync(0xffffffffu, e.x, j + 1);
            int   cc2 = __shfl_sync(0xffffffffu, e.x, j + 2);
            int   cc3 = __shfl_sync(0xffffffffu, e.x, j + 3);
            float vv0 = __int_as_float(__shfl_sync(0xffffffffu, e.y, j));
            float vv1 = __int_as_float(__shfl_sync(0xffffffffu, e.y, j + 1));
            float vv2 = __int_as_float(__shfl_sync(0xffffffffu, e.y, j + 2));
            float vv3 = __int_as_float(__shfl_sync(0xffffffffu, e.y, j + 3));
            float t0 = __half2float(T[(size_t)cc0 * F_OUT + lane]);
            float t1 = __half2float(T[(size_t)cc1 * F_OUT + lane]);
            float t2 = __half2float(T[(size_t)cc2 * F_OUT + lane]);
            float t3 = __half2float(T[(size_t)cc3 * F_OUT + lane]);
            acc = fmaf(t0, vv0, acc);
            acc = fmaf(t1, vv1, acc);
            acc = fmaf(t2, vv2, acc);
            acc = fmaf(t3, vv3, acc);
        }
    }
    float m = acc;
#pragma unroll
    for (int o = 16; o; o >>= 1) m = fmaxf(m, __shfl_xor_sync(0xffffffffu, m, o));
    float ex = expf(acc - m);
    float s = ex;
#pragma unroll
    for (int o = 16; o; o >>= 1) s += __shfl_xor_sync(0xffffffffu, s, o);
    out[(size_t)row * F_OUT + lane] = acc - m - logf(s);
}

// ---------------------------------------------------------------------------
extern "C" void kernel_launch(void* const* d_in, const int* in_sizes, int n_in,
                              void* d_out, int out_size) {
    const float* x    = (const float*)d_in[0];
    const int*   erow = (const int*)d_in[1];
    const int*   ecol = (const int*)d_in[2];
    const float* ev   = (const float*)d_in[3];
    const float* W1   = (const float*)d_in[4];
    const float* b1   = (const float*)d_in[5];
    const float* W2   = (const float*)d_in[6];
    const float* b2   = (const float*)d_in[7];
    float* out = (float*)d_out;

    const int M = in_sizes[0] / F_IN;   // 100000
    const int E = in_sizes[1];          // 3200000

    __half *support, *t;
    uint32_t* w1t;
    int2* edge;
    int *rowptr, *deg, *cursor, *bsum;
    cudaGetSymbolAddress((void**)&support, g_support);
    cudaGetSymbolAddress((void**)&t,       g_t);
    cudaGetSymbolAddress((void**)&w1t,     g_w1t);
    cudaGetSymbolAddress((void**)&rowptr,  g_rowptr);
    cudaGetSymbolAddress((void**)&deg,     g_deg);
    cudaGetSymbolAddress((void**)&cursor,  g_cursor);
    cudaGetSymbolAddress((void**)&bsum,    g_bsum);
    cudaGetSymbolAddress((void**)&edge,    g_edge);

    // One-time handle creation (on the uncaptured correctness call; reused
    // as-is during capture — record/wait edges express the fork/join).
    static cudaStream_t sB = nullptr;
    static cudaEvent_t  evFork = nullptr, evJoin = nullptr;
    if (sB == nullptr) {
        cudaStreamCreateWithFlags(&sB, cudaStreamNonBlocking);
        cudaEventCreateWithFlags(&evFork, cudaEventDisableTiming);
        cudaEventCreateWithFlags(&evJoin, cudaEventDisableTiming);
        cudaFuncSetAttribute(gemm1_tf32_kernel,
                             cudaFuncAttributeMaxDynamicSharedMemorySize,
                             G1_SMEM_BYTES);
    }

    const int nblk = (M + 1023) / 1024;

    // --- fork: GEMM branch on sB ---
    cudaEventRecord(evFork, 0);
    cudaStreamWaitEvent(sB, evFork, 0);
    w1conv_kernel<<<(F_IN * F_HID + 255) / 256, 256, 0, sB>>>(W1, w1t);
    gemm1_tf32_kernel<<<(M + 127) / 128, 256, G1_SMEM_BYTES, sB>>>(x, w1t,
                                                                   support, M);
    cudaEventRecord(evJoin, sB);

    // --- CSR build on default stream (concurrent with GEMM branch) ---
    cudaMemsetAsync(deg, 0, (size_t)M * sizeof(int));
    hist_kernel<<<(E + 255) / 256, 256>>>(erow, deg, E);
    scanA_kernel<<<nblk, 1024>>>(deg, rowptr, bsum, M);
    scanB_kernel<<<1, 256>>>(bsum, nblk);
    scanC_kernel<<<(M + 255) / 256, 256>>>(deg, rowptr, bsum, cursor, M);
    scatter_kernel<<<(E + 255) / 256, 256>>>(erow, ecol, ev, cursor, edge, E);

    // --- join, then fused SpMM stages ---
    cudaStreamWaitEvent(0, evJoin, 0);
    spmm1_gemm2_kernel<<<(M + 7) / 8, 256>>>(rowptr, edge, support, b1, W2, t, M);
    spmm2_lsm_kernel<<<(M + 7) / 8, 256>>>(rowptr, edge, t, b2, out, M);
}

// round 8
// speedup vs baseline: 3.7028x; 1.0760x over previous
#include <cuda_runtime.h>
#include <cuda_fp16.h>
#include <math.h>
#include <stdint.h>

#define N_NODES_MAX 100000
#define E_MAX       3300000
#define F_IN  512
#define F_HID 128
#define F_OUT 32

// Scratch (allocation-free rule: __device__ globals)
__device__ __half   g_support[(size_t)N_NODES_MAX * F_HID];  // x @ W1 (fp16)
__device__ __half   g_t[(size_t)N_NODES_MAX * F_OUT];        // relu(h)@W2 (fp16)
__device__ uint32_t g_w1t[F_IN * F_HID];  // W1^T as tf32 bits, [n][k]
__device__ int      g_rowptr[N_NODES_MAX + 1];
__device__ int      g_deg[N_NODES_MAX];
__device__ int      g_cursor[N_NODES_MAX];
__device__ int      g_bsum[256];
__device__ int2     g_edge[E_MAX];        // packed (col, val bits), row-sorted

__device__ __forceinline__ uint32_t f2tf32(float f) {
    uint32_t r;
    asm("cvt.rna.tf32.f32 %0, %1;" : "=r"(r) : "f"(f));
    return r;
}
__device__ __forceinline__ uint32_t smem_u32(const void* p) {
    uint32_t a;
    asm("{ .reg .u64 t; cvta.to.shared.u64 t, %1; cvt.u32.u64 %0, t; }"
        : "=r"(a) : "l"(p));
    return a;
}
__device__ __forceinline__ void cp16(uint32_t dst, const void* src, int srcsz) {
    asm volatile("cp.async.cg.shared.global [%0], [%1], 16, %2;"
                 :: "r"(dst), "l"(src), "r"(srcsz));
}
__device__ __forceinline__ void cp_commit() {
    asm volatile("cp.async.commit_group;" ::: "memory");
}
template <int N>
__device__ __forceinline__ void cp_wait() {
    asm volatile("cp.async.wait_group %0;" :: "n"(N) : "memory");
}

// ---------------------------------------------------------------------------
// W1 convert+transpose -> tf32 bits
// ---------------------------------------------------------------------------
__global__ void w1conv_kernel(const float* __restrict__ W1,
                              uint32_t* __restrict__ w1t) {
    int i = blockIdx.x * blockDim.x + threadIdx.x;
    if (i < F_IN * F_HID) {
        int k  = i >> 7;
        int nn = i & 127;
        w1t[nn * F_IN + k] = f2tf32(W1[i]);
    }
}

// ---------------------------------------------------------------------------
// CSR build
// ---------------------------------------------------------------------------
__global__ void hist_kernel(const int* __restrict__ erow, int* __restrict__ deg,
                            int E) {
    int e = blockIdx.x * blockDim.x + threadIdx.x;
    if (e < E) atomicAdd(&deg[erow[e]], 1);
}

__global__ __launch_bounds__(1024) void scanA_kernel(const int* __restrict__ deg,
                                                     int* __restrict__ rowptr,
                                                     int* __restrict__ bsum,
                                                     int n) {
    __shared__ int wsum[32];
    const int tid  = threadIdx.x;
    const int lane = tid & 31;
    const int wid  = tid >> 5;
    int i = blockIdx.x * 1024 + tid;
    int v = (i < n) ? deg[i] : 0;
    int x = v;
#pragma unroll
    for (int o = 1; o < 32; o <<= 1) {
        int t = __shfl_up_sync(0xffffffffu, x, o);
        if (lane >= o) x += t;
    }
    if (lane == 31) wsum[wid] = x;
    __syncthreads();
    if (wid == 0) {
        int w = wsum[lane];
#pragma unroll
        for (int o = 1; o < 32; o <<= 1) {
            int t = __shfl_up_sync(0xffffffffu, w, o);
            if (lane >= o) w += t;
        }
        wsum[lane] = w;
    }
    __syncthreads();
    int inc = x + (wid > 0 ? wsum[wid - 1] : 0);
    if (i < n) rowptr[i + 1] = inc;
    if (tid == 1023) bsum[blockIdx.x] = inc;
}

__global__ __launch_bounds__(256) void scanB_kernel(int* __restrict__ bsum,
                                                    int nblk) {
    __shared__ int wsum[8];
    const int tid  = threadIdx.x;
    const int lane = tid & 31;
    const int wid  = tid >> 5;
    int v = (tid < nblk) ? bsum[tid] : 0;
    int x = v;
#pragma unroll
    for (int o = 1; o < 32; o <<= 1) {
        int t = __shfl_up_sync(0xffffffffu, x, o);
        if (lane >= o) x += t;
    }
    if (lane == 31) wsum[wid] = x;
    __syncthreads();
    if (wid == 0 && lane < 8) {
        int w = wsum[lane];
#pragma unroll
        for (int o = 1; o < 8; o <<= 1) {
            int t = __shfl_up_sync(0xffu, w, o);
            if (lane >= o) w += t;
        }
        wsum[lane] = w;
    }
    __syncthreads();
    int inc = x + (wid > 0 ? wsum[wid - 1] : 0);
    if (tid < nblk) bsum[tid] = inc - v;
}

__global__ void scanC_kernel(const int* __restrict__ deg,
                             int* __restrict__ rowptr,
                             const int* __restrict__ bsum,
                             int* __restrict__ cursor, int n) {
    int i = blockIdx.x * blockDim.x + threadIdx.x;
    if (i >= n) return;
    int inc = rowptr[i + 1] + bsum[i >> 10];
    rowptr[i + 1] = inc;
    cursor[i] = inc - deg[i];
    if (i == 0) rowptr[0] = 0;
}

__global__ void scatter_kernel(const int* __restrict__ erow,
                               const int* __restrict__ ecol,
                               const float* __restrict__ ev,
                               int* __restrict__ cursor,
                               int2* __restrict__ edge, int E) {
    int e = blockIdx.x * blockDim.x + threadIdx.x;
    if (e >= E) return;
    int r = erow[e];
    int pos = atomicAdd(&cursor[r], 1);
    edge[pos] = make_int2(ecol[e], __float_as_int(ev[e]));
}

// ---------------------------------------------------------------------------
// GEMM1: S[M,128] = tf32(A[M,512]) @ tf32(W1) -> fp16 out.
// cp.async 2-stage pipeline, k-chunk 32 (72KB smem -> 2 CTAs/SM).
// Warp grid 4x2, warp tile 32 rows x 64 cols. A raw fp32 bits (HW tf32 trunc).
// ---------------------------------------------------------------------------
#define G1_STRIDE 36
#define G1_STAGE_WORDS (2 * 128 * G1_STRIDE)   // A + B per stage
#define G1_SMEM_BYTES  (2 * G1_STAGE_WORDS * 4)

extern __shared__ uint32_t g1smem[];

__global__ __launch_bounds__(256, 2) void gemm1_tf32_kernel(
    const float* __restrict__ A, const uint32_t* __restrict__ Wt,
    __half* __restrict__ S, int M) {
    const int tid  = threadIdx.x;
    const int lane = tid & 31;
    const int wid  = tid >> 5;
    const int wm   = wid >> 1;          // 0..3  (M direction, 32 rows each)
    const int wn   = wid & 1;           // 0..1  (N direction, 64 cols each)
    const int g    = lane >> 2;
    const int tg   = lane & 3;
    const int row0 = blockIdx.x * 128;

    float acc[2][8][4];
#pragma unroll
    for (int mt = 0; mt < 2; mt++)
#pragma unroll
        for (int nt = 0; nt < 8; nt++)
#pragma unroll
            for (int j = 0; j < 4; j++) acc[mt][nt][j] = 0.f;

    // load mapping: 256 threads, row = tid>>1 (0..127), 16 k-cols per thread
    const int lr   = tid >> 1;
    const int lc   = (tid & 1) * 16;
    const bool aok = (row0 + lr) < M;
    const int asz  = aok ? 16 : 0;
    const float*    Ag = A + (size_t)(row0 + lr) * F_IN + lc;
    const uint32_t* Bg = Wt + (size_t)lr * F_IN + lc;

    const uint32_t sbase = smem_u32(g1smem);
    uint32_t dA[2], dB[2];
#pragma unroll
    for (int s = 0; s < 2; s++) {
        dA[s] = sbase + (uint32_t)(s * G1_STAGE_WORDS + lr * G1_STRIDE + lc) * 4;
        dB[s] = dA[s] + (uint32_t)(128 * G1_STRIDE) * 4;
    }

#define G1_ISSUE(cc, st)                                                  \
    {                                                                     \
        const int kk = (cc) * 32;                                         \
        _Pragma("unroll")                                                 \
        for (int q = 0; q < 4; q++)                                       \
            cp16(dA[st] + q * 16, Ag + kk + q * 4, asz);                  \
        _Pragma("unroll")                                                 \
        for (int q = 0; q < 4; q++)                                       \
            cp16(dB[st] + q * 16, Bg + kk + q * 4, 16);                   \
    }

    G1_ISSUE(0, 0);
    cp_commit();

    for (int c = 0; c < 16; c++) {
        if (c < 15) {
            G1_ISSUE(c + 1, (c + 1) & 1);
            cp_commit();
            cp_wait<1>();
        } else {
            cp_wait<0>();
        }
        __syncthreads();

        const uint32_t* As = g1smem + (c & 1) * G1_STAGE_WORDS;
        const uint32_t* Bs = As + 128 * G1_STRIDE;
        const uint32_t* ap0 = As + (wm * 32 + g) * G1_STRIDE;       // rows +0/+8
        const uint32_t* ap1 = ap0 + 16 * G1_STRIDE;                 // rows +16/+24
#pragma unroll
        for (int ks = 0; ks < 4; ks++) {
            const int k = ks * 8;
            uint32_t a00 = ap0[k + tg];
            uint32_t a01 = ap0[8 * G1_STRIDE + k + tg];
            uint32_t a02 = ap0[k + tg + 4];
            uint32_t a03 = ap0[8 * G1_STRIDE + k + tg + 4];
            uint32_t a10 = ap1[k + tg];
            uint32_t a11 = ap1[8 * G1_STRIDE + k + tg];
            uint32_t a12 = ap1[k + tg + 4];
            uint32_t a13 = ap1[8 * G1_STRIDE + k + tg + 4];
#pragma unroll
            for (int nt = 0; nt < 8; nt++) {
                const uint32_t* bp = Bs + (wn * 64 + nt * 8 + g) * G1_STRIDE + k;
                uint32_t b0 = bp[tg];
                uint32_t b1 = bp[tg + 4];
                asm volatile(
                    "mma.sync.aligned.m16n8k8.row.col.f32.tf32.tf32.f32 "
                    "{%0,%1,%2,%3}, {%4,%5,%6,%7}, {%8,%9}, {%0,%1,%2,%3};"
                    : "+f"(acc[0][nt][0]), "+f"(acc[0][nt][1]),
                      "+f"(acc[0][nt][2]), "+f"(acc[0][nt][3])
                    : "r"(a00), "r"(a01), "r"(a02), "r"(a03), "r"(b0), "r"(b1));
                asm volatile(
                    "mma.sync.aligned.m16n8k8.row.col.f32.tf32.tf32.f32 "
                    "{%0,%1,%2,%3}, {%4,%5,%6,%7}, {%8,%9}, {%0,%1,%2,%3};"
                    : "+f"(acc[1][nt][0]), "+f"(acc[1][nt][1]),
                      "+f"(acc[1][nt][2]), "+f"(acc[1][nt][3])
                    : "r"(a10), "r"(a11), "r"(a12), "r"(a13), "r"(b0), "r"(b1));
            }
        }
        __syncthreads();
    }
#undef G1_ISSUE

#pragma unroll
    for (int mt = 0; mt < 2; mt++) {
        const int r0 = row0 + wm * 32 + mt * 16 + g;
        const int r1 = r0 + 8;
#pragma unroll
        for (int nt = 0; nt < 8; nt++) {
            const int col = wn * 64 + nt * 8 + 2 * tg;
            if (r0 < M)
                *(__half2*)&S[(size_t)r0 * F_HID + col] =
                    __floats2half2_rn(acc[mt][nt][0], acc[mt][nt][1]);
            if (r1 < M)
                *(__half2*)&S[(size_t)r1 * F_HID + col] =
                    __floats2half2_rn(acc[mt][nt][2], acc[mt][nt][3]);
        }
    }
}

// ---------------------------------------------------------------------------
// Fused: h = A @ support + b1 ; relu ; t = h @ W2 (fp16 out).
// ---------------------------------------------------------------------------
__global__ __launch_bounds__(256) void spmm1_gemm2_kernel(
    const int* __restrict__ rowptr, const int2* __restrict__ edge,
    const __half* __restrict__ S, const float* __restrict__ b1,
    const float* __restrict__ W2, __half* __restrict__ T, int M) {
    __shared__ float Ws[F_HID * F_OUT];
    const int tid = threadIdx.x;
    for (int i = tid; i < F_HID * F_OUT; i += 256) Ws[i] = W2[i];
    __syncthreads();

    const int lane = tid & 31;
    const int wid  = tid >> 5;
    const int row  = blockIdx.x * 8 + wid;
    if (row >= M) return;

    float4 hb = *(const float4*)(b1 + lane * 4);
    float h0 = hb.x, h1 = hb.y, h2 = hb.z, h3 = hb.w;

    const int start = rowptr[row];
    const int end   = rowptr[row + 1];
    for (int base = start; base < end; base += 32) {
        int idx = base + lane;
        int2 e = make_int2(0, 0);
        if (idx < end) e = edge[idx];
        int cnt = min(32, end - base);
        for (int j = 0; j < cnt; j += 4) {
            int   cc0 = __shfl_sync(0xffffffffu, e.x, j);
            int   cc1 = __shfl_sync(0xffffffffu, e.x, j + 1);
            int   cc2 = __shfl_sync(0xffffffffu, e.x, j + 2);
            int   cc3 = __shfl_sync(0xffffffffu, e.x, j + 3);
            float vv0 = __int_as_float(__shfl_sync(0xffffffffu, e.y, j));
            float vv1 = __int_as_float(__shfl_sync(0xffffffffu, e.y, j + 1));
            float vv2 = __int_as_float(__shfl_sync(0xffffffffu, e.y, j + 2));
            float vv3 = __int_as_float(__shfl_sync(0xffffffffu, e.y, j + 3));
            uint2 u0 = *(const uint2*)(S + (size_t)cc0 * F_HID + lane * 4);
            uint2 u1 = *(const uint2*)(S + (size_t)cc1 * F_HID + lane * 4);
            uint2 u2 = *(const uint2*)(S + (size_t)cc2 * F_HID + lane * 4);
            uint2 u3 = *(const uint2*)(S + (size_t)cc3 * F_HID + lane * 4);
#define ACC4(u, vv)                                                   \
            {                                                         \
                float2 fa = __half22float2(*(__half2*)&(u).x);        \
                float2 fb = __half22float2(*(__half2*)&(u).y);        \
                h0 = fmaf(fa.x, (vv), h0);                            \
                h1 = fmaf(fa.y, (vv), h1);                            \
                h2 = fmaf(fb.x, (vv), h2);                            \
                h3 = fmaf(fb.y, (vv), h3);                            \
            }
            ACC4(u0, vv0) ACC4(u1, vv1) ACC4(u2, vv2) ACC4(u3, vv3)
#undef ACC4
        }
    }
    h0 = fmaxf(h0, 0.f); h1 = fmaxf(h1, 0.f);
    h2 = fmaxf(h2, 0.f); h3 = fmaxf(h3, 0.f);

    float tacc = 0.f;
#pragma unroll 8
    for (int l = 0; l < 32; l++) {
        float a0 = __shfl_sync(0xffffffffu, h0, l);
        float a1 = __shfl_sync(0xffffffffu, h1, l);
        float a2 = __shfl_sync(0xffffffffu, h2, l);
        float a3 = __shfl_sync(0xffffffffu, h3, l);
        int k = l * 4;
        tacc = fmaf(a0, Ws[(k + 0) * F_OUT + lane], tacc);
        tacc = fmaf(a1, Ws[(k + 1) * F_OUT + lane], tacc);
        tacc = fmaf(a2, Ws[(k + 2) * F_OUT + lane], tacc);
        tacc = fmaf(a3, Ws[(k + 3) * F_OUT + lane], tacc);
    }
    T[(size_t)row * F_OUT + lane] = __float2half_rn(tacc);
}

// ---------------------------------------------------------------------------
// Fused: logits = A @ t + b2 ; log_softmax.
// ---------------------------------------------------------------------------
__global__ __launch_bounds__(256) void spmm2_lsm_kernel(
    const int* __restrict__ rowptr, const int2* __restrict__ edge,
    const __half* __restrict__ T, const float* __restrict__ b2,
    float* __restrict__ out, int M) {
    const int tid  = threadIdx.x;
    const int lane = tid & 31;
    const int wid  = tid >> 5;
    const int row  = blockIdx.x * 8 + wid;
    if (row >= M) return;

    float acc = b2[lane];
    const int start = rowptr[row];
    const int end   = rowptr[row + 1];
    for (int base = start; base < end; base += 32) {
        int idx = base + lane;
        int2 e = make_int2(0, 0);
        if (idx < end) e = edge[idx];
        int cnt = min(32, end - base);
        for (int j = 0; j < cnt; j += 4) {
            int   cc0 = __shfl_sync(0xffffffffu, e.x, j);
            int   cc1 = __shfl_sync(0xffffffffu, e.x, j + 1);
            int   cc2 = __shfl_sync(0xffffffffu, e.x, j + 2);
            int   cc3 = __shfl_sync(0xffffffffu, e.x, j + 3);
            float vv0 = __int_as_float(__shfl_sync(0xffffffffu, e.y, j));
            float vv1 = __int_as_float(__shfl_sync(0xffffffffu, e.y, j + 1));
            float vv2 = __int_as_float(__shfl_sync(0xffffffffu, e.y, j + 2));
            float vv3 = __int_as_float(__shfl_sync(0xffffffffu, e.y, j + 3));
            float t0 = __half2float(T[(size_t)cc0 * F_OUT + lane]);
            float t1 = __half2float(T[(size_t)cc1 * F_OUT + lane]);
            float t2 = __half2float(T[(size_t)cc2 * F_OUT + lane]);
            float t3 = __half2float(T[(size_t)cc3 * F_OUT + lane]);
            acc = fmaf(t0, vv0, acc);
            acc = fmaf(t1, vv1, acc);
            acc = fmaf(t2, vv2, acc);
            acc = fmaf(t3, vv3, acc);
        }
    }
    float m = acc;
#pragma unroll
    for (int o = 16; o; o >>= 1) m = fmaxf(m, __shfl_xor_sync(0xffffffffu, m, o));
    float ex = expf(acc - m);
    float s = ex;
#pragma unroll
    for (int o = 16; o; o >>= 1) s += __shfl_xor_sync(0xffffffffu, s, o);
    out[(size_t)row * F_OUT + lane] = acc - m - logf(s);
}

// ---------------------------------------------------------------------------
extern "C" void kernel_launch(void* const* d_in, const int* in_sizes, int n_in,
                              void* d_out, int out_size) {
    const float* x    = (const float*)d_in[0];
    const int*   erow = (const int*)d_in[1];
    const int*   ecol = (const int*)d_in[2];
    const float* ev   = (const float*)d_in[3];
    const float* W1   = (const float*)d_in[4];
    const float* b1   = (const float*)d_in[5];
    const float* W2   = (const float*)d_in[6];
    const float* b2   = (const float*)d_in[7];
    float* out = (float*)d_out;

    const int M = in_sizes[0] / F_IN;   // 100000
    const int E = in_sizes[1];          // 3200000

    __half *support, *t;
    uint32_t* w1t;
    int2* edge;
    int *rowptr, *deg, *cursor, *bsum;
    cudaGetSymbolAddress((void**)&support, g_support);
    cudaGetSymbolAddress((void**)&t,       g_t);
    cudaGetSymbolAddress((void**)&w1t,     g_w1t);
    cudaGetSymbolAddress((void**)&rowptr,  g_rowptr);
    cudaGetSymbolAddress((void**)&deg,     g_deg);
    cudaGetSymbolAddress((void**)&cursor,  g_cursor);
    cudaGetSymbolAddress((void**)&bsum,    g_bsum);
    cudaGetSymbolAddress((void**)&edge,    g_edge);

    static cudaStream_t sB = nullptr;
    static cudaEvent_t  evFork = nullptr, evJoin = nullptr;
    if (sB == nullptr) {
        cudaStreamCreateWithFlags(&sB, cudaStreamNonBlocking);
        cudaEventCreateWithFlags(&evFork, cudaEventDisableTiming);
        cudaEventCreateWithFlags(&evJoin, cudaEventDisableTiming);
        cudaFuncSetAttribute(gemm1_tf32_kernel,
                             cudaFuncAttributeMaxDynamicSharedMemorySize,
                             G1_SMEM_BYTES);
    }

    const int nblk = (M + 1023) / 1024;

    // --- fork: GEMM branch on sB (w1conv = launch 1) ---
    cudaEventRecord(evFork, 0);
    cudaStreamWaitEvent(sB, evFork, 0);
    w1conv_kernel<<<(F_IN * F_HID + 255) / 256, 256, 0, sB>>>(W1, w1t);

    // --- CSR build starts on default stream ---
    cudaMemsetAsync(deg, 0, (size_t)M * sizeof(int));
    hist_kernel<<<(E + 255) / 256, 256>>>(erow, deg, E);          // launch 2
    scanA_kernel<<<nblk, 1024>>>(deg, rowptr, bsum, M);           // launch 3

    // --- gemm1 = launch 4 (ncu capture target) ---
    gemm1_tf32_kernel<<<(M + 127) / 128, 256, G1_SMEM_BYTES, sB>>>(x, w1t,
                                                                   support, M);
    cudaEventRecord(evJoin, sB);

    scanB_kernel<<<1, 256>>>(bsum, nblk);                         // launch 5
    scanC_kernel<<<(M + 255) / 256, 256>>>(deg, rowptr, bsum, cursor, M);
    scatter_kernel<<<(E + 255) / 256, 256>>>(erow, ecol, ev, cursor, edge, E);

    // --- join, then fused SpMM stages ---
    cudaStreamWaitEvent(0, evJoin, 0);
    spmm1_gemm2_kernel<<<(M + 7) / 8, 256>>>(rowptr, edge, support, b1, W2, t, M);
    spmm2_lsm_kernel<<<(M + 7) / 8, 256>>>(rowptr, edge, t, b2, out, M);
}

// round 9
// speedup vs baseline: 3.9073x; 1.0552x over previous
#include <cuda_runtime.h>
#include <cuda_fp16.h>
#include <math.h>
#include <stdint.h>

#define N_NODES_MAX 100000
#define E_MAX       3300000
#define F_IN  512
#define F_HID 128
#define F_OUT 32

// Scratch (allocation-free rule: __device__ globals)
__device__ __half   g_support[(size_t)N_NODES_MAX * F_HID];  // x @ W1 (fp16)
__device__ __half   g_t[(size_t)N_NODES_MAX * F_OUT];        // relu(h)@W2 (fp16)
__device__ uint32_t g_w1t[F_IN * F_HID];  // W1^T as tf32 bits, [n][k]
__device__ int      g_rowptr[N_NODES_MAX + 1];
__device__ int      g_deg[N_NODES_MAX];
__device__ int      g_cursor[N_NODES_MAX];
__device__ int      g_bsum[256];
__device__ int2     g_edge[E_MAX];        // packed (col, val bits), row-sorted

__device__ __forceinline__ uint32_t f2tf32(float f) {
    uint32_t r;
    asm("cvt.rna.tf32.f32 %0, %1;" : "=r"(r) : "f"(f));
    return r;
}
__device__ __forceinline__ uint32_t smem_u32(const void* p) {
    uint32_t a;
    asm("{ .reg .u64 t; cvta.to.shared.u64 t, %1; cvt.u32.u64 %0, t; }"
        : "=r"(a) : "l"(p));
    return a;
}
__device__ __forceinline__ void cp16(uint32_t dst, const void* src, int srcsz) {
    asm volatile("cp.async.cg.shared.global [%0], [%1], 16, %2;"
                 :: "r"(dst), "l"(src), "r"(srcsz));
}
__device__ __forceinline__ void cp_commit() {
    asm volatile("cp.async.commit_group;" ::: "memory");
}
template <int N>
__device__ __forceinline__ void cp_wait() {
    asm volatile("cp.async.wait_group %0;" :: "n"(N) : "memory");
}

// ---------------------------------------------------------------------------
// W1 convert+transpose -> tf32 bits
// ---------------------------------------------------------------------------
__global__ void w1conv_kernel(const float* __restrict__ W1,
                              uint32_t* __restrict__ w1t) {
    int i = blockIdx.x * blockDim.x + threadIdx.x;
    if (i < F_IN * F_HID) {
        int k  = i >> 7;
        int nn = i & 127;
        w1t[nn * F_IN + k] = f2tf32(W1[i]);
    }
}

// ---------------------------------------------------------------------------
// CSR build
// ---------------------------------------------------------------------------
__global__ void hist_kernel(const int* __restrict__ erow, int* __restrict__ deg,
                            int E) {
    int e = blockIdx.x * blockDim.x + threadIdx.x;
    if (e < E) atomicAdd(&deg[erow[e]], 1);
}

__global__ __launch_bounds__(1024) void scanA_kernel(const int* __restrict__ deg,
                                                     int* __restrict__ rowptr,
                                                     int* __restrict__ bsum,
                                                     int n) {
    __shared__ int wsum[32];
    const int tid  = threadIdx.x;
    const int lane = tid & 31;
    const int wid  = tid >> 5;
    int i = blockIdx.x * 1024 + tid;
    int v = (i < n) ? deg[i] : 0;
    int x = v;
#pragma unroll
    for (int o = 1; o < 32; o <<= 1) {
        int t = __shfl_up_sync(0xffffffffu, x, o);
        if (lane >= o) x += t;
    }
    if (lane == 31) wsum[wid] = x;
    __syncthreads();
    if (wid == 0) {
        int w = wsum[lane];
#pragma unroll
        for (int o = 1; o < 32; o <<= 1) {
            int t = __shfl_up_sync(0xffffffffu, w, o);
            if (lane >= o) w += t;
        }
        wsum[lane] = w;
    }
    __syncthreads();
    int inc = x + (wid > 0 ? wsum[wid - 1] : 0);
    if (i < n) rowptr[i + 1] = inc;
    if (tid == 1023) bsum[blockIdx.x] = inc;
}

__global__ __launch_bounds__(256) void scanB_kernel(int* __restrict__ bsum,
                                                    int nblk) {
    __shared__ int wsum[8];
    const int tid  = threadIdx.x;
    const int lane = tid & 31;
    const int wid  = tid >> 5;
    int v = (tid < nblk) ? bsum[tid] : 0;
    int x = v;
#pragma unroll
    for (int o = 1; o < 32; o <<= 1) {
        int t = __shfl_up_sync(0xffffffffu, x, o);
        if (lane >= o) x += t;
    }
    if (lane == 31) wsum[wid] = x;
    __syncthreads();
    if (wid == 0 && lane < 8) {
        int w = wsum[lane];
#pragma unroll
        for (int o = 1; o < 8; o <<= 1) {
            int t = __shfl_up_sync(0xffu, w, o);
            if (lane >= o) w += t;
        }
        wsum[lane] = w;
    }
    __syncthreads();
    int inc = x + (wid > 0 ? wsum[wid - 1] : 0);
    if (tid < nblk) bsum[tid] = inc - v;
}

__global__ void scanC_kernel(const int* __restrict__ deg,
                             int* __restrict__ rowptr,
                             const int* __restrict__ bsum,
                             int* __restrict__ cursor, int n) {
    int i = blockIdx.x * blockDim.x + threadIdx.x;
    if (i >= n) return;
    int inc = rowptr[i + 1] + bsum[i >> 10];
    rowptr[i + 1] = inc;
    cursor[i] = inc - deg[i];
    if (i == 0) rowptr[0] = 0;
}

__global__ void scatter_kernel(const int* __restrict__ erow,
                               const int* __restrict__ ecol,
                               const float* __restrict__ ev,
                               int* __restrict__ cursor,
                               int2* __restrict__ edge, int E) {
    int e = blockIdx.x * blockDim.x + threadIdx.x;
    if (e >= E) return;
    int r = erow[e];
    int pos = atomicAdd(&cursor[r], 1);
    edge[pos] = make_int2(ecol[e], __float_as_int(ev[e]));
}

// ---------------------------------------------------------------------------
// GEMM1: S[M,128] = tf32(A[M,512]) @ tf32(W1) -> fp16 out.
// M-tile 256 (B refetch halved), 512 threads (16 warps, warp tile 32x64),
// k-chunk 32, 3-stage cp.async pipeline (162KB smem, 1 CTA/SM).
// ---------------------------------------------------------------------------
#define G1_STRIDE 36
#define G1_MROWS  256
#define G1_STAGE_WORDS ((G1_MROWS + 128) * G1_STRIDE)   // A(256) + B(128) rows
#define G1_SMEM_BYTES  (3 * G1_STAGE_WORDS * 4)

extern __shared__ uint32_t g1smem[];

__global__ __launch_bounds__(512, 1) void gemm1_tf32_kernel(
    const float* __restrict__ A, const uint32_t* __restrict__ Wt,
    __half* __restrict__ S, int M) {
    const int tid  = threadIdx.x;
    const int lane = tid & 31;
    const int wid  = tid >> 5;
    const int wm   = wid >> 1;          // 0..7  (M direction, 32 rows each)
    const int wn   = wid & 1;           // 0..1  (N direction, 64 cols each)
    const int g    = lane >> 2;
    const int tg   = lane & 3;
    const int row0 = blockIdx.x * G1_MROWS;

    float acc[2][8][4];
#pragma unroll
    for (int mt = 0; mt < 2; mt++)
#pragma unroll
        for (int nt = 0; nt < 8; nt++)
#pragma unroll
            for (int j = 0; j < 4; j++) acc[mt][nt][j] = 0.f;

    // A load mapping: 512 threads -> row tid>>1 (0..255), 16 words at (tid&1)*16
    const int lr   = tid >> 1;
    const int lc   = (tid & 1) * 16;
    const bool aok = (row0 + lr) < M;
    const int asz  = aok ? 16 : 0;
    const float* Ag = A + (size_t)(row0 + lr) * F_IN + lc;
    // B load mapping: row tid>>2 (0..127), 8 words at (tid&3)*8
    const int br = tid >> 2;
    const int bc = (tid & 3) * 8;
    const uint32_t* Bg = Wt + (size_t)br * F_IN + bc;

    const uint32_t sbase = smem_u32(g1smem);
    uint32_t dA[3], dB[3];
#pragma unroll
    for (int s = 0; s < 3; s++) {
        dA[s] = sbase + (uint32_t)(s * G1_STAGE_WORDS + lr * G1_STRIDE + lc) * 4;
        dB[s] = sbase + (uint32_t)(s * G1_STAGE_WORDS + G1_MROWS * G1_STRIDE +
                                   br * G1_STRIDE + bc) * 4;
    }

#define G1_ISSUE(cc, st)                                                  \
    {                                                                     \
        const int kk = (cc) * 32;                                         \
        _Pragma("unroll")                                                 \
        for (int q = 0; q < 4; q++)                                       \
            cp16(dA[st] + q * 16, Ag + kk + q * 4, asz);                  \
        _Pragma("unroll")                                                 \
        for (int q = 0; q < 2; q++)                                       \
            cp16(dB[st] + q * 16, Bg + kk + q * 4, 16);                   \
    }

    G1_ISSUE(0, 0); cp_commit();
    G1_ISSUE(1, 1); cp_commit();

    for (int c = 0; c < 16; c++) {
        if (c + 2 < 16) {
            G1_ISSUE(c + 2, (c + 2) % 3);
            cp_commit();
            cp_wait<2>();
        } else if (c + 1 < 16) {
            cp_wait<1>();
        } else {
            cp_wait<0>();
        }
        __syncthreads();

        const uint32_t* As = g1smem + (c % 3) * G1_STAGE_WORDS;
        const uint32_t* Bs = As + G1_MROWS * G1_STRIDE;
        const uint32_t* ap0 = As + (wm * 32 + g) * G1_STRIDE;       // rows +0/+8
        const uint32_t* ap1 = ap0 + 16 * G1_STRIDE;                 // rows +16/+24
#pragma unroll
        for (int ks = 0; ks < 4; ks++) {
            const int k = ks * 8;
            uint32_t a00 = ap0[k + tg];
            uint32_t a01 = ap0[8 * G1_STRIDE + k + tg];
            uint32_t a02 = ap0[k + tg + 4];
            uint32_t a03 = ap0[8 * G1_STRIDE + k + tg + 4];
            uint32_t a10 = ap1[k + tg];
            uint32_t a11 = ap1[8 * G1_STRIDE + k + tg];
            uint32_t a12 = ap1[k + tg + 4];
            uint32_t a13 = ap1[8 * G1_STRIDE + k + tg + 4];
#pragma unroll
            for (int nt = 0; nt < 8; nt++) {
                const uint32_t* bp = Bs + (wn * 64 + nt * 8 + g) * G1_STRIDE + k;
                uint32_t b0 = bp[tg];
                uint32_t b1 = bp[tg + 4];
                asm volatile(
                    "mma.sync.aligned.m16n8k8.row.col.f32.tf32.tf32.f32 "
                    "{%0,%1,%2,%3}, {%4,%5,%6,%7}, {%8,%9}, {%0,%1,%2,%3};"
                    : "+f"(acc[0][nt][0]), "+f"(acc[0][nt][1]),
                      "+f"(acc[0][nt][2]), "+f"(acc[0][nt][3])
                    : "r"(a00), "r"(a01), "r"(a02), "r"(a03), "r"(b0), "r"(b1));
                asm volatile(
                    "mma.sync.aligned.m16n8k8.row.col.f32.tf32.tf32.f32 "
                    "{%0,%1,%2,%3}, {%4,%5,%6,%7}, {%8,%9}, {%0,%1,%2,%3};"
                    : "+f"(acc[1][nt][0]), "+f"(acc[1][nt][1]),
                      "+f"(acc[1][nt][2]), "+f"(acc[1][nt][3])
                    : "r"(a10), "r"(a11), "r"(a12), "r"(a13), "r"(b0), "r"(b1));
            }
        }
        __syncthreads();
    }
#undef G1_ISSUE

#pragma unroll
    for (int mt = 0; mt < 2; mt++) {
        const int r0 = row0 + wm * 32 + mt * 16 + g;
        const int r1 = r0 + 8;
#pragma unroll
        for (int nt = 0; nt < 8; nt++) {
            const int col = wn * 64 + nt * 8 + 2 * tg;
            if (r0 < M)
                *(__half2*)&S[(size_t)r0 * F_HID + col] =
                    __floats2half2_rn(acc[mt][nt][0], acc[mt][nt][1]);
            if (r1 < M)
                *(__half2*)&S[(size_t)r1 * F_HID + col] =
                    __floats2half2_rn(acc[mt][nt][2], acc[mt][nt][3]);
        }
    }
}

// ---------------------------------------------------------------------------
// Fused: h = A @ support + b1 ; relu ; t = h @ W2 (fp16 out).
// ---------------------------------------------------------------------------
__global__ __launch_bounds__(256) void spmm1_gemm2_kernel(
    const int* __restrict__ rowptr, const int2* __restrict__ edge,
    const __half* __restrict__ S, const float* __restrict__ b1,
    const float* __restrict__ W2, __half* __restrict__ T, int M) {
    __shared__ float Ws[F_HID * F_OUT];
    const int tid = threadIdx.x;
    for (int i = tid; i < F_HID * F_OUT; i += 256) Ws[i] = W2[i];
    __syncthreads();

    const int lane = tid & 31;
    const int wid  = tid >> 5;
    const int row  = blockIdx.x * 8 + wid;
    if (row >= M) return;

    float4 hb = *(const float4*)(b1 + lane * 4);
    float h0 = hb.x, h1 = hb.y, h2 = hb.z, h3 = hb.w;

    const int start = rowptr[row];
    const int end   = rowptr[row + 1];
    for (int base = start; base < end; base += 32) {
        int idx = base + lane;
        int2 e = make_int2(0, 0);
        if (idx < end) e = edge[idx];
        int cnt = min(32, end - base);
        for (int j = 0; j < cnt; j += 4) {
            int   cc0 = __shfl_sync(0xffffffffu, e.x, j);
            int   cc1 = __shfl_sync(0xffffffffu, e.x, j + 1);
            int   cc2 = __shfl_sync(0xffffffffu, e.x, j + 2);
            int   cc3 = __shfl_sync(0xffffffffu, e.x, j + 3);
            float vv0 = __int_as_float(__shfl_sync(0xffffffffu, e.y, j));
            float vv1 = __int_as_float(__shfl_sync(0xffffffffu, e.y, j + 1));
            float vv2 = __int_as_float(__shfl_sync(0xffffffffu, e.y, j + 2));
            float vv3 = __int_as_float(__shfl_sync(0xffffffffu, e.y, j + 3));
            uint2 u0 = *(const uint2*)(S + (size_t)cc0 * F_HID + lane * 4);
            uint2 u1 = *(const uint2*)(S + (size_t)cc1 * F_HID + lane * 4);
            uint2 u2 = *(const uint2*)(S + (size_t)cc2 * F_HID + lane * 4);
            uint2 u3 = *(const uint2*)(S + (size_t)cc3 * F_HID + lane * 4);
#define ACC4(u, vv)                                                   \
            {                                                         \
                float2 fa = __half22float2(*(__half2*)&(u).x);        \
                float2 fb = __half22float2(*(__half2*)&(u).y);        \
                h0 = fmaf(fa.x, (vv), h0);                            \
                h1 = fmaf(fa.y, (vv), h1);                            \
                h2 = fmaf(fb.x, (vv), h2);                            \
                h3 = fmaf(fb.y, (vv), h3);                            \
            }
            ACC4(u0, vv0) ACC4(u1, vv1) ACC4(u2, vv2) ACC4(u3, vv3)
#undef ACC4
        }
    }
    h0 = fmaxf(h0, 0.f); h1 = fmaxf(h1, 0.f);
    h2 = fmaxf(h2, 0.f); h3 = fmaxf(h3, 0.f);

    float tacc = 0.f;
#pragma unroll 8
    for (int l = 0; l < 32; l++) {
        float a0 = __shfl_sync(0xffffffffu, h0, l);
        float a1 = __shfl_sync(0xffffffffu, h1, l);
        float a2 = __shfl_sync(0xffffffffu, h2, l);
        float a3 = __shfl_sync(0xffffffffu, h3, l);
        int k = l * 4;
        tacc = fmaf(a0, Ws[(k + 0) * F_OUT + lane], tacc);
        tacc = fmaf(a1, Ws[(k + 1) * F_OUT + lane], tacc);
        tacc = fmaf(a2, Ws[(k + 2) * F_OUT + lane], tacc);
        tacc = fmaf(a3, Ws[(k + 3) * F_OUT + lane], tacc);
    }
    T[(size_t)row * F_OUT + lane] = __float2half_rn(tacc);
}

// ---------------------------------------------------------------------------
// Fused: logits = A @ t + b2 ; log_softmax.
// ---------------------------------------------------------------------------
__global__ __launch_bounds__(256) void spmm2_lsm_kernel(
    const int* __restrict__ rowptr, const int2* __restrict__ edge,
    const __half* __restrict__ T, const float* __restrict__ b2,
    float* __restrict__ out, int M) {
    const int tid  = threadIdx.x;
    const int lane = tid & 31;
    const int wid  = tid >> 5;
    const int row  = blockIdx.x * 8 + wid;
    if (row >= M) return;

    float acc = b2[lane];
    const int start = rowptr[row];
    const int end   = rowptr[row + 1];
    for (int base = start; base < end; base += 32) {
        int idx = base + lane;
        int2 e = make_int2(0, 0);
        if (idx < end) e = edge[idx];
        int cnt = min(32, end - base);
        for (int j = 0; j < cnt; j += 4) {
            int   cc0 = __shfl_sync(0xffffffffu, e.x, j);
            int   cc1 = __shfl_sync(0xffffffffu, e.x, j + 1);
            int   cc2 = __shfl_sync(0xffffffffu, e.x, j + 2);
            int   cc3 = __shfl_sync(0xffffffffu, e.x, j + 3);
            float vv0 = __int_as_float(__shfl_sync(0xffffffffu, e.y, j));
            float vv1 = __int_as_float(__shfl_sync(0xffffffffu, e.y, j + 1));
            float vv2 = __int_as_float(__shfl_sync(0xffffffffu, e.y, j + 2));
            float vv3 = __int_as_float(__shfl_sync(0xffffffffu, e.y, j + 3));
            float t0 = __half2float(T[(size_t)cc0 * F_OUT + lane]);
            float t1 = __half2float(T[(size_t)cc1 * F_OUT + lane]);
            float t2 = __half2float(T[(size_t)cc2 * F_OUT + lane]);
            float t3 = __half2float(T[(size_t)cc3 * F_OUT + lane]);
            acc = fmaf(t0, vv0, acc);
            acc = fmaf(t1, vv1, acc);
            acc = fmaf(t2, vv2, acc);
            acc = fmaf(t3, vv3, acc);
        }
    }
    float m = acc;
#pragma unroll
    for (int o = 16; o; o >>= 1) m = fmaxf(m, __shfl_xor_sync(0xffffffffu, m, o));
    float ex = expf(acc - m);
    float s = ex;
#pragma unroll
    for (int o = 16; o; o >>= 1) s += __shfl_xor_sync(0xffffffffu, s, o);
    out[(size_t)row * F_OUT + lane] = acc - m - logf(s);
}

// ---------------------------------------------------------------------------
extern "C" void kernel_launch(void* const* d_in, const int* in_sizes, int n_in,
                              void* d_out, int out_size) {
    const float* x    = (const float*)d_in[0];
    const int*   erow = (const int*)d_in[1];
    const int*   ecol = (const int*)d_in[2];
    const float* ev   = (const float*)d_in[3];
    const float* W1   = (const float*)d_in[4];
    const float* b1   = (const float*)d_in[5];
    const float* W2   = (const float*)d_in[6];
    const float* b2   = (const float*)d_in[7];
    float* out = (float*)d_out;

    const int M = in_sizes[0] / F_IN;   // 100000
    const int E = in_sizes[1];          // 3200000

    __half *support, *t;
    uint32_t* w1t;
    int2* edge;
    int *rowptr, *deg, *cursor, *bsum;
    cudaGetSymbolAddress((void**)&support, g_support);
    cudaGetSymbolAddress((void**)&t,       g_t);
    cudaGetSymbolAddress((void**)&w1t,     g_w1t);
    cudaGetSymbolAddress((void**)&rowptr,  g_rowptr);
    cudaGetSymbolAddress((void**)&deg,     g_deg);
    cudaGetSymbolAddress((void**)&cursor,  g_cursor);
    cudaGetSymbolAddress((void**)&bsum,    g_bsum);
    cudaGetSymbolAddress((void**)&edge,    g_edge);

    static cudaStream_t sB = nullptr;
    static cudaEvent_t  evFork = nullptr, evJoin = nullptr;
    if (sB == nullptr) {
        cudaStreamCreateWithFlags(&sB, cudaStreamNonBlocking);
        cudaEventCreateWithFlags(&evFork, cudaEventDisableTiming);
        cudaEventCreateWithFlags(&evJoin, cudaEventDisableTiming);
        cudaFuncSetAttribute(gemm1_tf32_kernel,
                             cudaFuncAttributeMaxDynamicSharedMemorySize,
                             G1_SMEM_BYTES);
    }

    const int nblk = (M + 1023) / 1024;

    // --- fork: GEMM branch on sB (w1conv = launch 1) ---
    cudaEventRecord(evFork, 0);
    cudaStreamWaitEvent(sB, evFork, 0);
    w1conv_kernel<<<(F_IN * F_HID + 255) / 256, 256, 0, sB>>>(W1, w1t);

    // --- CSR build starts on default stream ---
    cudaMemsetAsync(deg, 0, (size_t)M * sizeof(int));
    hist_kernel<<<(E + 255) / 256, 256>>>(erow, deg, E);          // launch 2
    scanA_kernel<<<nblk, 1024>>>(deg, rowptr, bsum, M);           // launch 3

    // --- gemm1 = launch 4 (ncu capture target) ---
    gemm1_tf32_kernel<<<(M + G1_MROWS - 1) / G1_MROWS, 512, G1_SMEM_BYTES, sB>>>(
        x, w1t, support, M);
    cudaEventRecord(evJoin, sB);

    scanB_kernel<<<1, 256>>>(bsum, nblk);                         // launch 5
    scanC_kernel<<<(M + 255) / 256, 256>>>(deg, rowptr, bsum, cursor, M);
    scatter_kernel<<<(E + 255) / 256, 256>>>(erow, ecol, ev, cursor, edge, E);

    // --- join, then fused SpMM stages ---
    cudaStreamWaitEvent(0, evJoin, 0);
    spmm1_gemm2_kernel<<<(M + 7) / 8, 256>>>(rowptr, edge, support, b1, W2, t, M);
    spmm2_lsm_kernel<<<(M + 7) / 8, 256>>>(rowptr, edge, t, b2, out, M);
}